// round 8
// baseline (speedup 1.0000x reference)
#include <cuda_runtime.h>
#include <cuda_bf16.h>
#include <cuda_fp16.h>
#include <math.h>

#define NN 50000
#define EE 800000
#define FD 256
#define NH 4
#define HF 64
#define K2 (FD / 2)       // 128 packed bf16x2 per row

// ---------------- scratch ----------------
__device__ __half   g_h  [NN * FD];          // per-layer projection (fp16)
__device__ unsigned g_ahi[NN * K2];          // layer input, bf16 hi packed (k,k+1)
__device__ unsigned g_alo[NN * K2];          // layer input, bf16 lo packed
__device__ unsigned g_whi[3 * K2 * FD];      // weights pre-packed [layer][k2][n]
__device__ unsigned g_wlo[3 * K2 * FD];
__device__ float    g_als[NN * NH];
__device__ float    g_ald[NN * NH];
__device__ int      g_deg[NN];
__device__ int      g_rowptr[NN + 1];
__device__ int      g_cursor[NN];
__device__ int      g_srcs[EE];

__device__ __forceinline__ void split2(float x, float y, unsigned& hi, unsigned& lo) {
    __nv_bfloat16 hx = __float2bfloat16(x);
    __nv_bfloat16 hy = __float2bfloat16(y);
    float rx = x - __bfloat162float(hx);
    float ry = y - __bfloat162float(hy);
    __nv_bfloat162 h2 = __halves2bfloat162(hx, hy);
    __nv_bfloat162 l2 = __floats2bfloat162_rn(rx, ry);
    hi = *(unsigned*)&h2;
    lo = *(unsigned*)&l2;
}

// ---------------- CSR build ----------------
__global__ void deg_zero_k(int* __restrict__ deg) {
    int i = blockIdx.x * blockDim.x + threadIdx.x;
    if (i < NN) deg[i] = 0;
}
__global__ void deg_hist_k(const int* __restrict__ ei, int* __restrict__ deg) {
    int e = blockIdx.x * blockDim.x + threadIdx.x;
    if (e < EE) atomicAdd(deg + ei[EE + e], 1);
}
__global__ __launch_bounds__(1024) void scan_k(const int* __restrict__ deg,
                                               int* __restrict__ rowptr,
                                               int* __restrict__ cursor) {
    __shared__ int ssum[1024];
    const int CH = 49;
    int t = threadIdx.x;
    int base = t * CH;
    int s = 0;
    for (int i = 0; i < CH; i++) {
        int idx = base + i;
        if (idx < NN) s += deg[idx];
    }
    ssum[t] = s;
    __syncthreads();
    for (int o = 1; o < 1024; o <<= 1) {
        int u = (t >= o) ? ssum[t - o] : 0;
        __syncthreads();
        ssum[t] += u;
        __syncthreads();
    }
    int run = ssum[t] - s;
    for (int i = 0; i < CH; i++) {
        int idx = base + i;
        if (idx <= NN) {
            if (idx < NN) {
                rowptr[idx] = run;
                cursor[idx] = run;
                run += deg[idx];
            } else {
                rowptr[NN] = run;
            }
        }
    }
}
__global__ void fill_k(const int* __restrict__ ei, int* __restrict__ cursor,
                       int* __restrict__ srcs) {
    int e = blockIdx.x * blockDim.x + threadIdx.x;
    if (e >= EE) return;
    int dst = ei[EE + e];
    int pos = atomicAdd(cursor + dst, 1);
    srcs[pos] = ei[e];
}

// ---------------- operand pre-split ----------------
__global__ void split_x_k(const float* __restrict__ x,
                          unsigned* __restrict__ hi, unsigned* __restrict__ lo) {
    int idx = blockIdx.x * blockDim.x + threadIdx.x;
    if (idx >= NN * 64) return;
    float4 v = ((const float4*)x)[idx];
    unsigned h0, l0, h1, l1;
    split2(v.x, v.y, h0, l0);
    split2(v.z, v.w, h1, l1);
    ((uint2*)hi)[idx] = make_uint2(h0, h1);
    ((uint2*)lo)[idx] = make_uint2(l0, l1);
}
__global__ void split_w_k(const float* __restrict__ W0, const float* __restrict__ W1,
                          const float* __restrict__ W2,
                          unsigned* __restrict__ hi, unsigned* __restrict__ lo) {
    int idx = blockIdx.x * blockDim.x + threadIdx.x;
    if (idx >= 3 * K2 * FD) return;
    int l = idx / (K2 * FD);
    int rem = idx - l * (K2 * FD);
    int k2 = rem >> 8, n = rem & 255;
    const float* W = (l == 0) ? W0 : (l == 1) ? W1 : W2;
    float a = W[(2 * k2) * FD + n];
    float b = W[(2 * k2 + 1) * FD + n];
    unsigned h, lw;
    split2(a, b, h, lw);
    hi[idx] = h;
    lo[idx] = lw;
}

// ---------------- BF16x3 GEMM, 2-stage cp.async, fp16 output ----------------
// BM=128, BN=128, BK=16 (8 k2) per stage. 256 threads, warp tile 64x32.
#define SA2 12    // A smem row stride in uints (8 + 4 pad) -> conflict-free frags
#define SB2 136   // B smem row stride in uints (128 + 8 pad) -> conflict-free frags
#define NIT (K2 / 8)   // 16 k-iterations

#define MMA_BF16(c, a, b) \
    asm volatile("mma.sync.aligned.m16n8k16.row.col.f32.bf16.bf16.f32 " \
                 "{%0,%1,%2,%3}, {%4,%5,%6,%7}, {%8,%9}, {%0,%1,%2,%3};" \
                 : "+f"(c[0]), "+f"(c[1]), "+f"(c[2]), "+f"(c[3]) \
                 : "r"(a[0]), "r"(a[1]), "r"(a[2]), "r"(a[3]), "r"(b[0]), "r"(b[1]))

__device__ __forceinline__ void cp16(unsigned dst, const void* src, bool pred) {
    int bytes = pred ? 16 : 0;
    asm volatile("cp.async.cg.shared.global [%0], [%1], 16, %2;"
                 :: "r"(dst), "l"(src), "r"(bytes));
}
#define CP_COMMIT() asm volatile("cp.async.commit_group;")
#define CP_WAIT(n)  asm volatile("cp.async.wait_group %0;" :: "n"(n))

__global__ __launch_bounds__(256) void gemm_pre_k(
    const unsigned* __restrict__ Ahi, const unsigned* __restrict__ Alo,
    const unsigned* __restrict__ Whi, const unsigned* __restrict__ Wlo,
    __half* __restrict__ C, int N)
{
    __shared__ unsigned Ah2[2 * 128 * SA2], Al2[2 * 128 * SA2];
    __shared__ unsigned Bh2[2 * 8 * SB2],   Bl2[2 * 8 * SB2];
    int tid = threadIdx.x, lane = tid & 31, wid = tid >> 5;
    int bm = blockIdx.x * 128, bn = blockIdx.y * 128;
    int wm = (wid >> 2) * 64, wn = (wid & 3) * 32;
    int gr = lane >> 2, gc = lane & 3;

    unsigned sAh = (unsigned)__cvta_generic_to_shared(Ah2);
    unsigned sAl = (unsigned)__cvta_generic_to_shared(Al2);
    unsigned sBh = (unsigned)__cvta_generic_to_shared(Bh2);
    unsigned sBl = (unsigned)__cvta_generic_to_shared(Bl2);

    // per-thread load slots
    int ar = tid >> 1, ac = (tid & 1) * 4;       // A: 128 rows x 2 uint4
    int br = tid >> 5, bc = (tid & 31) * 4;      // B: 8 rows x 32 uint4
    bool ap = (bm + ar) < N;
    size_t abase = (size_t)(bm + ar) * K2 + ac;
    size_t bbase = (size_t)br * FD + bn + bc;

    float acc[4][4][4] = {};

#define LOAD_STAGE(kb, s) do { \
        cp16(sAh + (unsigned)(((s) * 128 * SA2 + ar * SA2 + ac) * 4), Ahi + abase + (kb), ap); \
        cp16(sAl + (unsigned)(((s) * 128 * SA2 + ar * SA2 + ac) * 4), Alo + abase + (kb), ap); \
        cp16(sBh + (unsigned)(((s) * 8 * SB2 + br * SB2 + bc) * 4), Whi + bbase + (size_t)(kb) * FD, true); \
        cp16(sBl + (unsigned)(((s) * 8 * SB2 + br * SB2 + bc) * 4), Wlo + bbase + (size_t)(kb) * FD, true); \
    } while (0)

    LOAD_STAGE(0, 0); CP_COMMIT();
    LOAD_STAGE(8, 1); CP_COMMIT();

    for (int it = 0; it < NIT; it++) {
        if (it < NIT - 1) { CP_WAIT(1); } else { CP_WAIT(0); }
        __syncthreads();
        int s = it & 1;
        const unsigned* As = Ah2 + s * 128 * SA2;
        const unsigned* Als = Al2 + s * 128 * SA2;
        const unsigned* Bs = Bh2 + s * 8 * SB2;
        const unsigned* Bls = Bl2 + s * 8 * SB2;

        unsigned ah[4][4], al[4][4], bh[4][2], bl[4][2];
        #pragma unroll
        for (int mt = 0; mt < 4; mt++) {
            int m = wm + mt * 16 + gr;
            const unsigned* p = As + m * SA2 + gc;
            const unsigned* q = Als + m * SA2 + gc;
            ah[mt][0] = p[0]; ah[mt][1] = p[8 * SA2]; ah[mt][2] = p[4]; ah[mt][3] = p[8 * SA2 + 4];
            al[mt][0] = q[0]; al[mt][1] = q[8 * SA2]; al[mt][2] = q[4]; al[mt][3] = q[8 * SA2 + 4];
        }
        #pragma unroll
        for (int nt = 0; nt < 4; nt++) {
            int n = wn + nt * 8 + gr;
            const unsigned* p = Bs + gc * SB2 + n;
            const unsigned* q = Bls + gc * SB2 + n;
            bh[nt][0] = p[0]; bh[nt][1] = p[4 * SB2];
            bl[nt][0] = q[0]; bl[nt][1] = q[4 * SB2];
        }
        #pragma unroll
        for (int mt = 0; mt < 4; mt++)
            #pragma unroll
            for (int nt = 0; nt < 4; nt++) {
                MMA_BF16(acc[mt][nt], ah[mt], bh[nt]);
                MMA_BF16(acc[mt][nt], ah[mt], bl[nt]);
                MMA_BF16(acc[mt][nt], al[mt], bh[nt]);
            }
        __syncthreads();
        if (it + 2 < NIT) { LOAD_STAGE((it + 2) * 8, s); CP_COMMIT(); }
    }

    #pragma unroll
    for (int mt = 0; mt < 4; mt++)
        #pragma unroll
        for (int nt = 0; nt < 4; nt++) {
            int row = bm + wm + mt * 16 + gr;
            int col = bn + wn + nt * 8 + 2 * gc;
            if (row < N)
                *(__half2*)(C + (size_t)row * FD + col) =
                    __floats2half2_rn(acc[mt][nt][0], acc[mt][nt][1]);
            if (row + 8 < N)
                *(__half2*)(C + (size_t)(row + 8) * FD + col) =
                    __floats2half2_rn(acc[mt][nt][2], acc[mt][nt][3]);
        }
}

// ---------------- attention logits: warp per (node, head), fp16 h ----------------
__global__ void att_k(const __half* __restrict__ h,
                      const float* __restrict__ a_s, const float* __restrict__ a_d,
                      float* __restrict__ als, float* __restrict__ ald, int N)
{
    int w = (blockIdx.x * blockDim.x + threadIdx.x) >> 5;
    int lane = threadIdx.x & 31;
    if (w >= N * NH) return;
    int n = w >> 2, hd = w & 3;
    const __half2* hp = (const __half2*)(h + (size_t)n * FD + hd * HF);
    const float* sp = a_s + hd * HF;
    const float* dp = a_d + hd * HF;
    float2 v = __half22float2(hp[lane]);
    int e = 2 * lane;
    float s = v.x * sp[e] + v.y * sp[e + 1];
    float d = v.x * dp[e] + v.y * dp[e + 1];
    #pragma unroll
    for (int o = 16; o; o >>= 1) {
        s += __shfl_xor_sync(0xffffffffu, s, o);
        d += __shfl_xor_sync(0xffffffffu, d, o);
    }
    if (lane == 0) { als[n * NH + hd] = s; ald[n * NH + hd] = d; }
}

// ---------------- fused gather: 2 warps per dst node, fp16 h ----------------
__device__ __forceinline__ float lrelu(float x) { return x > 0.f ? x : 0.2f * x; }

__device__ __forceinline__ float4 ld_h4(const uint2* hp, size_t idx) {
    uint2 u = hp[idx];
    __half2 p0 = *(__half2*)&u.x, p1 = *(__half2*)&u.y;
    float2 f0 = __half22float2(p0), f1 = __half22float2(p1);
    return make_float4(f0.x, f0.y, f1.x, f1.y);
}

__global__ __launch_bounds__(256) void gather_k(
    const int* __restrict__ rowptr, const int* __restrict__ srcs,
    const float* __restrict__ als, const float* __restrict__ ald,
    const __half* __restrict__ h, const float* __restrict__ bias,
    float* __restrict__ out_f32,
    unsigned* __restrict__ out_hi, unsigned* __restrict__ out_lo,
    int final_layer)
{
    int w = (blockIdx.x * blockDim.x + threadIdx.x) >> 5;
    int lane = threadIdx.x & 31;
    if (w >= NN * 2) return;
    int dst = w >> 1, half = w & 1;
    int f4 = half * 32 + lane;                 // 4-float group index within 64-wide row
    int hd = half * 2 + (lane >> 4);
    float aldv = __ldg(ald + dst * NH + hd);
    const uint2* hp = (const uint2*)h;         // 4 halves per uint2, 64 per row

    float4 acc = make_float4(0.f, 0.f, 0.f, 0.f);
    float den = 0.f;

    // self loop
    {
        float ee = __expf(lrelu(__ldg(als + dst * NH + hd) + aldv));
        float4 v = ld_h4(hp, (size_t)dst * 64 + f4);
        acc.x += ee * v.x; acc.y += ee * v.y; acc.z += ee * v.z; acc.w += ee * v.w;
        den += ee;
    }

    int beg = rowptr[dst], end = rowptr[dst + 1];
    int i = beg;
    for (; i + 2 <= end; i += 2) {
        int s0 = __ldg(srcs + i), s1 = __ldg(srcs + i + 1);
        float e0 = __expf(lrelu(__ldg(als + s0 * NH + hd) + aldv));
        float e1 = __expf(lrelu(__ldg(als + s1 * NH + hd) + aldv));
        float4 v0 = ld_h4(hp, (size_t)s0 * 64 + f4);
        float4 v1 = ld_h4(hp, (size_t)s1 * 64 + f4);
        acc.x += e0 * v0.x + e1 * v1.x;
        acc.y += e0 * v0.y + e1 * v1.y;
        acc.z += e0 * v0.z + e1 * v1.z;
        acc.w += e0 * v0.w + e1 * v1.w;
        den += e0 + e1;
    }
    if (i < end) {
        int s0 = __ldg(srcs + i);
        float e0 = __expf(lrelu(__ldg(als + s0 * NH + hd) + aldv));
        float4 v0 = ld_h4(hp, (size_t)s0 * 64 + f4);
        acc.x += e0 * v0.x; acc.y += e0 * v0.y; acc.z += e0 * v0.z; acc.w += e0 * v0.w;
        den += e0;
    }

    float inv = 1.f / (den + 1e-16f);
    float4 b = ((const float4*)bias)[f4];
    float4 o;
    o.x = acc.x * inv + b.x; o.y = acc.y * inv + b.y;
    o.z = acc.z * inv + b.z; o.w = acc.w * inv + b.w;
    if (final_layer) {
        ((float4*)out_f32)[(size_t)dst * 64 + f4] = o;
    } else {
        unsigned h0, l0, h1, l1;
        split2(o.x, o.y, h0, l0);
        split2(o.z, o.w, h1, l1);
        ((uint2*)out_hi)[(size_t)dst * 64 + f4] = make_uint2(h0, h1);
        ((uint2*)out_lo)[(size_t)dst * 64 + f4] = make_uint2(l0, l1);
    }
}

// ---------------- host side ----------------
static void run_layer(const unsigned* whi, const unsigned* wlo,
                      const float* a_s, const float* a_d, const float* b,
                      const int* rowptr, const int* srcs,
                      unsigned* ahi, unsigned* alo,
                      __half* h, float* als, float* ald,
                      float* out_f32, int final_layer)
{
    int N = NN;
    dim3 ggrid((N + 127) / 128, FD / 128);
    gemm_pre_k<<<ggrid, 256>>>(ahi, alo, whi, wlo, h, N);
    att_k<<<(N * NH * 32 + 255) / 256, 256>>>(h, a_s, a_d, als, ald, N);
    gather_k<<<(N * 2 * 32 + 255) / 256, 256>>>(rowptr, srcs, als, ald, h, b,
                                                out_f32, ahi, alo, final_layer);
}

extern "C" void kernel_launch(void* const* d_in, const int* in_sizes, int n_in,
                              void* d_out, int out_size)
{
    const float* x   = (const float*)d_in[0];
    const int*   ei  = (const int*)  d_in[1];
    const float* W0  = (const float*)d_in[2];
    const float* as0 = (const float*)d_in[3];
    const float* ad0 = (const float*)d_in[4];
    const float* b0  = (const float*)d_in[5];
    const float* W1  = (const float*)d_in[6];
    const float* as1 = (const float*)d_in[7];
    const float* ad1 = (const float*)d_in[8];
    const float* b1  = (const float*)d_in[9];
    const float* W2  = (const float*)d_in[10];
    const float* as2 = (const float*)d_in[11];
    const float* ad2 = (const float*)d_in[12];
    const float* b2  = (const float*)d_in[13];
    float* out = (float*)d_out;

    void *ph, *pahi, *palo, *pwhi, *pwlo, *pals, *pald, *pdeg, *prp, *pcur, *psrc;
    cudaGetSymbolAddress(&ph,   g_h);
    cudaGetSymbolAddress(&pahi, g_ahi);
    cudaGetSymbolAddress(&palo, g_alo);
    cudaGetSymbolAddress(&pwhi, g_whi);
    cudaGetSymbolAddress(&pwlo, g_wlo);
    cudaGetSymbolAddress(&pals, g_als);
    cudaGetSymbolAddress(&pald, g_ald);
    cudaGetSymbolAddress(&pdeg, g_deg);
    cudaGetSymbolAddress(&prp,  g_rowptr);
    cudaGetSymbolAddress(&pcur, g_cursor);
    cudaGetSymbolAddress(&psrc, g_srcs);

    __half* h     = (__half*)ph;
    unsigned* ahi = (unsigned*)pahi;
    unsigned* alo = (unsigned*)palo;
    unsigned* whi = (unsigned*)pwhi;
    unsigned* wlo = (unsigned*)pwlo;
    float* als    = (float*)pals;
    float* ald    = (float*)pald;
    int* deg      = (int*)pdeg;
    int* rowptr   = (int*)prp;
    int* cursor   = (int*)pcur;
    int* srcs     = (int*)psrc;

    // CSR build
    deg_zero_k<<<(NN + 255) / 256, 256>>>(deg);
    deg_hist_k<<<(EE + 255) / 256, 256>>>(ei, deg);
    scan_k<<<1, 1024>>>(deg, rowptr, cursor);
    fill_k<<<(EE + 255) / 256, 256>>>(ei, cursor, srcs);

    // operand pre-split
    split_x_k<<<(NN * 64 + 255) / 256, 256>>>(x, ahi, alo);
    split_w_k<<<(3 * K2 * FD + 255) / 256, 256>>>(W0, W1, W2, whi, wlo);

    run_layer(whi,               wlo,               as0, ad0, b0, rowptr, srcs, ahi, alo, h, als, ald, out, 0);
    run_layer(whi + K2 * FD,     wlo + K2 * FD,     as1, ad1, b1, rowptr, srcs, ahi, alo, h, als, ald, out, 0);
    run_layer(whi + 2 * K2 * FD, wlo + 2 * K2 * FD, as2, ad2, b2, rowptr, srcs, ahi, alo, h, als, ald, out, 1);
}

// round 9
// speedup vs baseline: 1.1399x; 1.1399x over previous
#include <cuda_runtime.h>
#include <cuda_bf16.h>
#include <cuda_fp16.h>
#include <math.h>

#define NN 50000
#define EE 800000
#define FD 256
#define NH 4
#define HF 64
#define K2 (FD / 2)       // 128 packed bf16x2 per row

// ---------------- scratch ----------------
__device__ __half   g_h  [NN * FD];          // per-layer projection (fp16)
__device__ unsigned g_ahi[NN * K2];          // layer input, bf16 hi packed (k,k+1)
__device__ unsigned g_alo[NN * K2];          // layer input, bf16 lo packed
__device__ unsigned g_whi[3 * K2 * FD];      // weights pre-packed [layer][k2][n]
__device__ unsigned g_wlo[3 * K2 * FD];
__device__ float    g_als[NN * NH];
__device__ float    g_ald[NN * NH];
__device__ int      g_deg[NN];
__device__ int      g_rowptr[NN + 1];
__device__ int      g_cursor[NN];
__device__ int      g_srcs[EE];

__device__ __forceinline__ void split2(float x, float y, unsigned& hi, unsigned& lo) {
    __nv_bfloat16 hx = __float2bfloat16(x);
    __nv_bfloat16 hy = __float2bfloat16(y);
    float rx = x - __bfloat162float(hx);
    float ry = y - __bfloat162float(hy);
    __nv_bfloat162 h2 = __halves2bfloat162(hx, hy);
    __nv_bfloat162 l2 = __floats2bfloat162_rn(rx, ry);
    hi = *(unsigned*)&h2;
    lo = *(unsigned*)&l2;
}

// ---------------- prep: deg=0, split x, split W (one kernel) ----------------
__global__ void prep_k(const float* __restrict__ x,
                       unsigned* __restrict__ xhi, unsigned* __restrict__ xlo,
                       const float* __restrict__ W0, const float* __restrict__ W1,
                       const float* __restrict__ W2,
                       unsigned* __restrict__ whi, unsigned* __restrict__ wlo,
                       int* __restrict__ deg)
{
    int idx = blockIdx.x * blockDim.x + threadIdx.x;
    if (idx < NN) deg[idx] = 0;
    if (idx < 3 * K2 * FD) {
        int l = idx / (K2 * FD);
        int rem = idx - l * (K2 * FD);
        int k2 = rem >> 8, n = rem & 255;
        const float* W = (l == 0) ? W0 : (l == 1) ? W1 : W2;
        float a = W[(2 * k2) * FD + n];
        float b = W[(2 * k2 + 1) * FD + n];
        unsigned h, lw;
        split2(a, b, h, lw);
        whi[idx] = h;
        wlo[idx] = lw;
    }
    if (idx < NN * 64) {
        float4 v = ((const float4*)x)[idx];
        unsigned h0, l0, h1, l1;
        split2(v.x, v.y, h0, l0);
        split2(v.z, v.w, h1, l1);
        ((uint2*)xhi)[idx] = make_uint2(h0, h1);
        ((uint2*)xlo)[idx] = make_uint2(l0, l1);
    }
}

// ---------------- CSR build ----------------
__global__ void deg_hist_k(const int* __restrict__ ei, int* __restrict__ deg) {
    int e = blockIdx.x * blockDim.x + threadIdx.x;
    if (e < EE) atomicAdd(deg + ei[EE + e], 1);
}
__global__ __launch_bounds__(1024) void scan_k(const int* __restrict__ deg,
                                               int* __restrict__ rowptr,
                                               int* __restrict__ cursor) {
    __shared__ int ssum[1024];
    const int CH = 49;
    int t = threadIdx.x;
    int base = t * CH;
    int s = 0;
    for (int i = 0; i < CH; i++) {
        int idx = base + i;
        if (idx < NN) s += deg[idx];
    }
    ssum[t] = s;
    __syncthreads();
    for (int o = 1; o < 1024; o <<= 1) {
        int u = (t >= o) ? ssum[t - o] : 0;
        __syncthreads();
        ssum[t] += u;
        __syncthreads();
    }
    int run = ssum[t] - s;
    for (int i = 0; i < CH; i++) {
        int idx = base + i;
        if (idx <= NN) {
            if (idx < NN) {
                rowptr[idx] = run;
                cursor[idx] = run;
                run += deg[idx];
            } else {
                rowptr[NN] = run;
            }
        }
    }
}
__global__ void fill_k(const int* __restrict__ ei, int* __restrict__ cursor,
                       int* __restrict__ srcs) {
    int e = blockIdx.x * blockDim.x + threadIdx.x;
    if (e >= EE) return;
    int dst = ei[EE + e];
    int pos = atomicAdd(cursor + dst, 1);
    srcs[pos] = ei[e];
}

// ---------------- BF16x3 GEMM, 2-stage cp.async, fp16 output ----------------
#define SA2 12    // A smem row stride in uints (8 + 4 pad)
#define SB2 136   // B smem row stride in uints (128 + 8 pad)
#define NIT (K2 / 8)   // 16 k-iterations

#define MMA_BF16(c, a, b) \
    asm volatile("mma.sync.aligned.m16n8k16.row.col.f32.bf16.bf16.f32 " \
                 "{%0,%1,%2,%3}, {%4,%5,%6,%7}, {%8,%9}, {%0,%1,%2,%3};" \
                 : "+f"(c[0]), "+f"(c[1]), "+f"(c[2]), "+f"(c[3]) \
                 : "r"(a[0]), "r"(a[1]), "r"(a[2]), "r"(a[3]), "r"(b[0]), "r"(b[1]))

__device__ __forceinline__ void cp16(unsigned dst, const void* src, bool pred) {
    int bytes = pred ? 16 : 0;
    asm volatile("cp.async.cg.shared.global [%0], [%1], 16, %2;"
                 :: "r"(dst), "l"(src), "r"(bytes));
}
#define CP_COMMIT() asm volatile("cp.async.commit_group;")
#define CP_WAIT(n)  asm volatile("cp.async.wait_group %0;" :: "n"(n))

__global__ __launch_bounds__(256) void gemm_pre_k(
    const unsigned* __restrict__ Ahi, const unsigned* __restrict__ Alo,
    const unsigned* __restrict__ Whi, const unsigned* __restrict__ Wlo,
    __half* __restrict__ C, int N)
{
    __shared__ unsigned Ah2[2 * 128 * SA2], Al2[2 * 128 * SA2];
    __shared__ unsigned Bh2[2 * 8 * SB2],   Bl2[2 * 8 * SB2];
    int tid = threadIdx.x, lane = tid & 31, wid = tid >> 5;
    int bm = blockIdx.x * 128, bn = blockIdx.y * 128;
    int wm = (wid >> 2) * 64, wn = (wid & 3) * 32;
    int gr = lane >> 2, gc = lane & 3;

    unsigned sAh = (unsigned)__cvta_generic_to_shared(Ah2);
    unsigned sAl = (unsigned)__cvta_generic_to_shared(Al2);
    unsigned sBh = (unsigned)__cvta_generic_to_shared(Bh2);
    unsigned sBl = (unsigned)__cvta_generic_to_shared(Bl2);

    int ar = tid >> 1, ac = (tid & 1) * 4;
    int br = tid >> 5, bc = (tid & 31) * 4;
    bool ap = (bm + ar) < N;
    size_t abase = (size_t)(bm + ar) * K2 + ac;
    size_t bbase = (size_t)br * FD + bn + bc;

    float acc[4][4][4] = {};

#define LOAD_STAGE(kb, s) do { \
        cp16(sAh + (unsigned)(((s) * 128 * SA2 + ar * SA2 + ac) * 4), Ahi + abase + (kb), ap); \
        cp16(sAl + (unsigned)(((s) * 128 * SA2 + ar * SA2 + ac) * 4), Alo + abase + (kb), ap); \
        cp16(sBh + (unsigned)(((s) * 8 * SB2 + br * SB2 + bc) * 4), Whi + bbase + (size_t)(kb) * FD, true); \
        cp16(sBl + (unsigned)(((s) * 8 * SB2 + br * SB2 + bc) * 4), Wlo + bbase + (size_t)(kb) * FD, true); \
    } while (0)

    LOAD_STAGE(0, 0); CP_COMMIT();
    LOAD_STAGE(8, 1); CP_COMMIT();

    for (int it = 0; it < NIT; it++) {
        if (it < NIT - 1) { CP_WAIT(1); } else { CP_WAIT(0); }
        __syncthreads();
        int s = it & 1;
        const unsigned* As = Ah2 + s * 128 * SA2;
        const unsigned* Als = Al2 + s * 128 * SA2;
        const unsigned* Bs = Bh2 + s * 8 * SB2;
        const unsigned* Bls = Bl2 + s * 8 * SB2;

        unsigned ah[4][4], al[4][4], bh[4][2], bl[4][2];
        #pragma unroll
        for (int mt = 0; mt < 4; mt++) {
            int m = wm + mt * 16 + gr;
            const unsigned* p = As + m * SA2 + gc;
            const unsigned* q = Als + m * SA2 + gc;
            ah[mt][0] = p[0]; ah[mt][1] = p[8 * SA2]; ah[mt][2] = p[4]; ah[mt][3] = p[8 * SA2 + 4];
            al[mt][0] = q[0]; al[mt][1] = q[8 * SA2]; al[mt][2] = q[4]; al[mt][3] = q[8 * SA2 + 4];
        }
        #pragma unroll
        for (int nt = 0; nt < 4; nt++) {
            int n = wn + nt * 8 + gr;
            const unsigned* p = Bs + gc * SB2 + n;
            const unsigned* q = Bls + gc * SB2 + n;
            bh[nt][0] = p[0]; bh[nt][1] = p[4 * SB2];
            bl[nt][0] = q[0]; bl[nt][1] = q[4 * SB2];
        }
        #pragma unroll
        for (int mt = 0; mt < 4; mt++)
            #pragma unroll
            for (int nt = 0; nt < 4; nt++) {
                MMA_BF16(acc[mt][nt], ah[mt], bh[nt]);
                MMA_BF16(acc[mt][nt], ah[mt], bl[nt]);
                MMA_BF16(acc[mt][nt], al[mt], bh[nt]);
            }
        __syncthreads();
        if (it + 2 < NIT) { LOAD_STAGE((it + 2) * 8, s); CP_COMMIT(); }
    }

    #pragma unroll
    for (int mt = 0; mt < 4; mt++)
        #pragma unroll
        for (int nt = 0; nt < 4; nt++) {
            int row = bm + wm + mt * 16 + gr;
            int col = bn + wn + nt * 8 + 2 * gc;
            if (row < N)
                *(__half2*)(C + (size_t)row * FD + col) =
                    __floats2half2_rn(acc[mt][nt][0], acc[mt][nt][1]);
            if (row + 8 < N)
                *(__half2*)(C + (size_t)(row + 8) * FD + col) =
                    __floats2half2_rn(acc[mt][nt][2], acc[mt][nt][3]);
        }
}

// ---------------- attention logits: warp per (node, head), fp16 h ----------------
__global__ void att_k(const __half* __restrict__ h,
                      const float* __restrict__ a_s, const float* __restrict__ a_d,
                      float* __restrict__ als, float* __restrict__ ald, int N)
{
    int w = (blockIdx.x * blockDim.x + threadIdx.x) >> 5;
    int lane = threadIdx.x & 31;
    if (w >= N * NH) return;
    int n = w >> 2, hd = w & 3;
    const __half2* hp = (const __half2*)(h + (size_t)n * FD + hd * HF);
    const float* sp = a_s + hd * HF;
    const float* dp = a_d + hd * HF;
    float2 v = __half22float2(hp[lane]);
    int e = 2 * lane;
    float s = v.x * sp[e] + v.y * sp[e + 1];
    float d = v.x * dp[e] + v.y * dp[e + 1];
    #pragma unroll
    for (int o = 16; o; o >>= 1) {
        s += __shfl_xor_sync(0xffffffffu, s, o);
        d += __shfl_xor_sync(0xffffffffu, d, o);
    }
    if (lane == 0) { als[n * NH + hd] = s; ald[n * NH + hd] = d; }
}

// ---------------- fused gather: ONE warp per dst node ----------------
__device__ __forceinline__ float lrelu(float x) { return x > 0.f ? x : 0.2f * x; }

// load 8 fp16 features as floats
struct F8 { float v[8]; };
__device__ __forceinline__ F8 ld_h8(const uint4* hp, size_t idx) {
    uint4 u = hp[idx];
    F8 r;
    float2 f;
    f = __half22float2(*(__half2*)&u.x); r.v[0] = f.x; r.v[1] = f.y;
    f = __half22float2(*(__half2*)&u.y); r.v[2] = f.x; r.v[3] = f.y;
    f = __half22float2(*(__half2*)&u.z); r.v[4] = f.x; r.v[5] = f.y;
    f = __half22float2(*(__half2*)&u.w); r.v[6] = f.x; r.v[7] = f.y;
    return r;
}

__global__ __launch_bounds__(256) void gather_k(
    const int* __restrict__ rowptr, const int* __restrict__ srcs,
    const float* __restrict__ als, const float* __restrict__ ald,
    const __half* __restrict__ h, const float* __restrict__ bias,
    float* __restrict__ out_f32,
    unsigned* __restrict__ out_hi, unsigned* __restrict__ out_lo,
    int final_layer)
{
    int w = (blockIdx.x * blockDim.x + threadIdx.x) >> 5;
    int lane = threadIdx.x & 31;
    if (w >= NN) return;
    int dst = w;
    int hd = lane >> 3;                        // 8 features per lane -> one head
    float aldv = __ldg(ald + dst * NH + hd);
    const uint4* hp = (const uint4*)h;         // 8 halves per uint4, 32 per row

    float acc[8] = {};
    float den = 0.f;

    // self loop
    {
        float ee = __expf(lrelu(__ldg(als + dst * NH + hd) + aldv));
        F8 v = ld_h8(hp, (size_t)dst * 32 + lane);
        #pragma unroll
        for (int j = 0; j < 8; j++) acc[j] += ee * v.v[j];
        den += ee;
    }

    int beg = rowptr[dst], end = rowptr[dst + 1];
    int i = beg;
    for (; i + 2 <= end; i += 2) {
        int s0 = __ldg(srcs + i), s1 = __ldg(srcs + i + 1);
        float e0 = __expf(lrelu(__ldg(als + s0 * NH + hd) + aldv));
        float e1 = __expf(lrelu(__ldg(als + s1 * NH + hd) + aldv));
        F8 v0 = ld_h8(hp, (size_t)s0 * 32 + lane);
        F8 v1 = ld_h8(hp, (size_t)s1 * 32 + lane);
        #pragma unroll
        for (int j = 0; j < 8; j++) acc[j] += e0 * v0.v[j] + e1 * v1.v[j];
        den += e0 + e1;
    }
    if (i < end) {
        int s0 = __ldg(srcs + i);
        float e0 = __expf(lrelu(__ldg(als + s0 * NH + hd) + aldv));
        F8 v0 = ld_h8(hp, (size_t)s0 * 32 + lane);
        #pragma unroll
        for (int j = 0; j < 8; j++) acc[j] += e0 * v0.v[j];
        den += e0;
    }

    float inv = 1.f / (den + 1e-16f);
    const float4* bp = (const float4*)bias;    // 64 float4 per row
    float4 b0 = bp[lane * 2], b1 = bp[lane * 2 + 1];
    float o[8];
    o[0] = acc[0] * inv + b0.x; o[1] = acc[1] * inv + b0.y;
    o[2] = acc[2] * inv + b0.z; o[3] = acc[3] * inv + b0.w;
    o[4] = acc[4] * inv + b1.x; o[5] = acc[5] * inv + b1.y;
    o[6] = acc[6] * inv + b1.z; o[7] = acc[7] * inv + b1.w;

    if (final_layer) {
        float4* op = (float4*)(out_f32 + (size_t)dst * FD);
        op[lane * 2]     = make_float4(o[0], o[1], o[2], o[3]);
        op[lane * 2 + 1] = make_float4(o[4], o[5], o[6], o[7]);
    } else {
        unsigned h0, l0, h1, l1, h2, l2, h3, l3;
        split2(o[0], o[1], h0, l0);
        split2(o[2], o[3], h1, l1);
        split2(o[4], o[5], h2, l2);
        split2(o[6], o[7], h3, l3);
        uint4* ph = (uint4*)(out_hi + (size_t)dst * K2);
        uint4* pl = (uint4*)(out_lo + (size_t)dst * K2);
        ph[lane] = make_uint4(h0, h1, h2, h3);
        pl[lane] = make_uint4(l0, l1, l2, l3);
    }
}

// ---------------- host side ----------------
extern "C" void kernel_launch(void* const* d_in, const int* in_sizes, int n_in,
                              void* d_out, int out_size)
{
    const float* x   = (const float*)d_in[0];
    const int*   ei  = (const int*)  d_in[1];
    const float* W0  = (const float*)d_in[2];
    const float* as0 = (const float*)d_in[3];
    const float* ad0 = (const float*)d_in[4];
    const float* b0  = (const float*)d_in[5];
    const float* W1  = (const float*)d_in[6];
    const float* as1 = (const float*)d_in[7];
    const float* ad1 = (const float*)d_in[8];
    const float* b1  = (const float*)d_in[9];
    const float* W2  = (const float*)d_in[10];
    const float* as2 = (const float*)d_in[11];
    const float* ad2 = (const float*)d_in[12];
    const float* b2  = (const float*)d_in[13];
    float* out = (float*)d_out;

    void *ph, *pahi, *palo, *pwhi, *pwlo, *pals, *pald, *pdeg, *prp, *pcur, *psrc;
    cudaGetSymbolAddress(&ph,   g_h);
    cudaGetSymbolAddress(&pahi, g_ahi);
    cudaGetSymbolAddress(&palo, g_alo);
    cudaGetSymbolAddress(&pwhi, g_whi);
    cudaGetSymbolAddress(&pwlo, g_wlo);
    cudaGetSymbolAddress(&pals, g_als);
    cudaGetSymbolAddress(&pald, g_ald);
    cudaGetSymbolAddress(&pdeg, g_deg);
    cudaGetSymbolAddress(&prp,  g_rowptr);
    cudaGetSymbolAddress(&pcur, g_cursor);
    cudaGetSymbolAddress(&psrc, g_srcs);

    __half* h     = (__half*)ph;
    unsigned* ahi = (unsigned*)pahi;
    unsigned* alo = (unsigned*)palo;
    unsigned* whi = (unsigned*)pwhi;
    unsigned* wlo = (unsigned*)pwlo;
    float* als    = (float*)pals;
    float* ald    = (float*)pald;
    int* deg      = (int*)pdeg;
    int* rowptr   = (int*)prp;
    int* cursor   = (int*)pcur;
    int* srcs     = (int*)psrc;

    dim3 ggrid((NN + 127) / 128, FD / 128);

    // 1: prep (deg zero + splits)
    prep_k<<<(NN * 64 + 255) / 256, 256>>>(x, ahi, alo, W0, W1, W2, whi, wlo, deg);
    // 2: hist
    deg_hist_k<<<(EE + 255) / 256, 256>>>(ei, deg);
    // 3: scan
    scan_k<<<1, 1024>>>(deg, rowptr, cursor);
    // 4: layer-0 GEMM  <-- ncu capture lands here
    gemm_pre_k<<<ggrid, 256>>>(ahi, alo, whi, wlo, h, NN);
    // 5: CSR fill (needed only by gather, launch 7)
    fill_k<<<(EE + 255) / 256, 256>>>(ei, cursor, srcs);
    // 6..: rest of layer 0
    att_k<<<(NN * NH * 32 + 255) / 256, 256>>>(h, as0, ad0, als, ald, NN);
    gather_k<<<(NN * 32 + 255) / 256, 256>>>(rowptr, srcs, als, ald, h, b0, out, ahi, alo, 0);
    // layer 1
    gemm_pre_k<<<ggrid, 256>>>(ahi, alo, whi + K2 * FD, wlo + K2 * FD, h, NN);
    att_k<<<(NN * NH * 32 + 255) / 256, 256>>>(h, as1, ad1, als, ald, NN);
    gather_k<<<(NN * 32 + 255) / 256, 256>>>(rowptr, srcs, als, ald, h, b1, out, ahi, alo, 0);
    // layer 2
    gemm_pre_k<<<ggrid, 256>>>(ahi, alo, whi + 2 * K2 * FD, wlo + 2 * K2 * FD, h, NN);
    att_k<<<(NN * NH * 32 + 255) / 256, 256>>>(h, as2, ad2, als, ald, NN);
    gather_k<<<(NN * 32 + 255) / 256, 256>>>(rowptr, srcs, als, ald, h, b2, out, ahi, alo, 1);
}

// round 12
// speedup vs baseline: 1.2760x; 1.1193x over previous
#include <cuda_runtime.h>
#include <cuda_fp16.h>
#include <math.h>

#define NN 50000
#define EE 800000
#define FD 256
#define NH 4
#define HF 64
#define K2 (FD / 2)       // 128 packed fp16x2 per row

// ---------------- scratch ----------------
__device__ __half   g_h  [NN * FD];          // per-layer projection (fp16)
__device__ unsigned g_in [NN * K2];          // layer input, fp16 packed (k,k+1)
__device__ unsigned g_whi[3 * K2 * FD];      // W pre-packed [layer][k2][n] fp16 hi
__device__ unsigned g_wlo[3 * K2 * FD];      // W fp16 lo (residual)
__device__ float    g_als[NN * NH];
__device__ float    g_ald[NN * NH];
__device__ int      g_deg[NN];
__device__ int      g_rowptr[NN + 1];
__device__ int      g_cursor[NN];
__device__ int      g_srcs[EE];

__device__ __forceinline__ void splitw(float x, float y, unsigned& hi, unsigned& lo) {
    __half hx = __float2half_rn(x);
    __half hy = __float2half_rn(y);
    float rx = x - __half2float(hx);
    float ry = y - __half2float(hy);
    __half2 h2 = __halves2half2(hx, hy);
    __half2 l2 = __floats2half2_rn(rx, ry);
    hi = *(unsigned*)&h2;
    lo = *(unsigned*)&l2;
}

// ---------------- prep: deg=0, x->fp16, split W (one kernel) ----------------
__global__ void prep_k(const float* __restrict__ x,
                       unsigned* __restrict__ xin,
                       const float* __restrict__ W0, const float* __restrict__ W1,
                       const float* __restrict__ W2,
                       unsigned* __restrict__ whi, unsigned* __restrict__ wlo,
                       int* __restrict__ deg)
{
    int idx = blockIdx.x * blockDim.x + threadIdx.x;
    if (idx < NN) deg[idx] = 0;
    if (idx < 3 * K2 * FD) {
        // layout: [l][k2][n]  (k-pairs packed)
        int l = idx / (K2 * FD);
        int rem = idx - l * (K2 * FD);
        int k2 = rem >> 8, n = rem & 255;
        const float* W = (l == 0) ? W0 : (l == 1) ? W1 : W2;
        float a = W[(2 * k2) * FD + n];
        float b = W[(2 * k2 + 1) * FD + n];
        unsigned h, lw;
        splitw(a, b, h, lw);
        whi[idx] = h;
        wlo[idx] = lw;
    }
    if (idx < NN * 64) {
        float4 v = ((const float4*)x)[idx];
        __half2 p0 = __floats2half2_rn(v.x, v.y);
        __half2 p1 = __floats2half2_rn(v.z, v.w);
        ((uint2*)xin)[idx] = make_uint2(*(unsigned*)&p0, *(unsigned*)&p1);
    }
}

// ---------------- CSR build ----------------
__global__ void deg_hist_k(const int* __restrict__ ei, int* __restrict__ deg) {
    int e = blockIdx.x * blockDim.x + threadIdx.x;
    if (e < EE) atomicAdd(deg + ei[EE + e], 1);
}
__global__ __launch_bounds__(1024) void scan_k(const int* __restrict__ deg,
                                               int* __restrict__ rowptr,
                                               int* __restrict__ cursor) {
    __shared__ int ssum[1024];
    const int CH = 49;
    int t = threadIdx.x;
    int base = t * CH;
    int s = 0;
    for (int i = 0; i < CH; i++) {
        int idx = base + i;
        if (idx < NN) s += deg[idx];
    }
    ssum[t] = s;
    __syncthreads();
    for (int o = 1; o < 1024; o <<= 1) {
        int u = (t >= o) ? ssum[t - o] : 0;
        __syncthreads();
        ssum[t] += u;
        __syncthreads();
    }
    int run = ssum[t] - s;
    for (int i = 0; i < CH; i++) {
        int idx = base + i;
        if (idx <= NN) {
            if (idx < NN) {
                rowptr[idx] = run;
                cursor[idx] = run;
                run += deg[idx];
            } else {
                rowptr[NN] = run;
            }
        }
    }
}
__global__ void fill_k(const int* __restrict__ ei, int* __restrict__ cursor,
                       int* __restrict__ srcs) {
    int e = blockIdx.x * blockDim.x + threadIdx.x;
    if (e >= EE) return;
    int dst = ei[EE + e];
    int pos = atomicAdd(cursor + dst, 1);
    srcs[pos] = ei[e];
}

// ---------------- fp16x2-W GEMM, 2-stage cp.async, fp16 in/out ----------------
// C[N,256] = A[N,256](fp16) * (Wh + Wl)[256,256]
// BM=128, BN=128, BK=16 (8 k2) per stage. 256 threads, warp tile 64x32.
#define SA2 12    // A smem row stride in uints (8 + 4 pad)
#define SB2 136   // B smem row stride in uints (128 + 8 pad)
#define NIT (K2 / 8)   // 16 k-iterations

#define MMA_F16(c, a, b) \
    asm volatile("mma.sync.aligned.m16n8k16.row.col.f32.f16.f16.f32 " \
                 "{%0,%1,%2,%3}, {%4,%5,%6,%7}, {%8,%9}, {%0,%1,%2,%3};" \
                 : "+f"(c[0]), "+f"(c[1]), "+f"(c[2]), "+f"(c[3]) \
                 : "r"(a[0]), "r"(a[1]), "r"(a[2]), "r"(a[3]), "r"(b[0]), "r"(b[1]))

__device__ __forceinline__ void cp16(unsigned dst, const void* src, bool pred) {
    int bytes = pred ? 16 : 0;
    asm volatile("cp.async.cg.shared.global [%0], [%1], 16, %2;"
                 :: "r"(dst), "l"(src), "r"(bytes));
}
#define CP_COMMIT() asm volatile("cp.async.commit_group;")
#define CP_WAIT(n)  asm volatile("cp.async.wait_group %0;" :: "n"(n))

__global__ __launch_bounds__(256) void gemm_pre_k(
    const unsigned* __restrict__ Ain,
    const unsigned* __restrict__ Whi, const unsigned* __restrict__ Wlo,
    __half* __restrict__ C, int N)
{
    __shared__ unsigned As2[2 * 128 * SA2];
    __shared__ unsigned Bh2[2 * 8 * SB2], Bl2[2 * 8 * SB2];
    int tid = threadIdx.x, lane = tid & 31, wid = tid >> 5;
    int bm = blockIdx.x * 128, bn = blockIdx.y * 128;
    int wm = (wid >> 2) * 64, wn = (wid & 3) * 32;
    int gr = lane >> 2, gc = lane & 3;

    unsigned sA  = (unsigned)__cvta_generic_to_shared(As2);
    unsigned sBh = (unsigned)__cvta_generic_to_shared(Bh2);
    unsigned sBl = (unsigned)__cvta_generic_to_shared(Bl2);

    int ar = tid >> 1, ac = (tid & 1) * 4;       // A: 128 rows x 2 uint4
    int br = tid >> 5, bc = (tid & 31) * 4;      // B: 8 rows x 32 uint4
    bool ap = (bm + ar) < N;
    size_t abase = (size_t)(bm + ar) * K2 + ac;
    size_t bbase = (size_t)br * FD + bn + bc;

    float acc[4][4][4] = {};

#define LOAD_STAGE(kb, s) do { \
        cp16(sA  + (unsigned)(((s) * 128 * SA2 + ar * SA2 + ac) * 4), Ain + abase + (kb), ap); \
        cp16(sBh + (unsigned)(((s) * 8 * SB2 + br * SB2 + bc) * 4), Whi + bbase + (size_t)(kb) * FD, true); \
        cp16(sBl + (unsigned)(((s) * 8 * SB2 + br * SB2 + bc) * 4), Wlo + bbase + (size_t)(kb) * FD, true); \
    } while (0)

    LOAD_STAGE(0, 0); CP_COMMIT();
    LOAD_STAGE(8, 1); CP_COMMIT();

    for (int it = 0; it < NIT; it++) {
        if (it < NIT - 1) { CP_WAIT(1); } else { CP_WAIT(0); }
        __syncthreads();
        int s = it & 1;
        const unsigned* As = As2 + s * 128 * SA2;
        const unsigned* Bs = Bh2 + s * 8 * SB2;
        const unsigned* Bls = Bl2 + s * 8 * SB2;

        unsigned ah[4][4], bh[4][2], bl[4][2];
        #pragma unroll
        for (int mt = 0; mt < 4; mt++) {
            int m = wm + mt * 16 + gr;
            const unsigned* p = As + m * SA2 + gc;
            ah[mt][0] = p[0]; ah[mt][1] = p[8 * SA2]; ah[mt][2] = p[4]; ah[mt][3] = p[8 * SA2 + 4];
        }
        #pragma unroll
        for (int nt = 0; nt < 4; nt++) {
            int n = wn + nt * 8 + gr;
            const unsigned* p = Bs + gc * SB2 + n;
            const unsigned* q = Bls + gc * SB2 + n;
            bh[nt][0] = p[0]; bh[nt][1] = p[4 * SB2];
            bl[nt][0] = q[0]; bl[nt][1] = q[4 * SB2];
        }
        #pragma unroll
        for (int mt = 0; mt < 4; mt++)
            #pragma unroll
            for (int nt = 0; nt < 4; nt++) {
                MMA_F16(acc[mt][nt], ah[mt], bh[nt]);
                MMA_F16(acc[mt][nt], ah[mt], bl[nt]);
            }
        __syncthreads();
        if (it + 2 < NIT) { LOAD_STAGE((it + 2) * 8, s); CP_COMMIT(); }
    }

    #pragma unroll
    for (int mt = 0; mt < 4; mt++)
        #pragma unroll
        for (int nt = 0; nt < 4; nt++) {
            int row = bm + wm + mt * 16 + gr;
            int col = bn + wn + nt * 8 + 2 * gc;
            if (row < N)
                *(__half2*)(C + (size_t)row * FD + col) =
                    __floats2half2_rn(acc[mt][nt][0], acc[mt][nt][1]);
            if (row + 8 < N)
                *(__half2*)(C + (size_t)(row + 8) * FD + col) =
                    __floats2half2_rn(acc[mt][nt][2], acc[mt][nt][3]);
        }
}

// ---------------- attention logits: warp per (node, head), fp16 h ----------------
__global__ void att_k(const __half* __restrict__ h,
                      const float* __restrict__ a_s, const float* __restrict__ a_d,
                      float* __restrict__ als, float* __restrict__ ald, int N)
{
    int w = (blockIdx.x * blockDim.x + threadIdx.x) >> 5;
    int lane = threadIdx.x & 31;
    if (w >= N * NH) return;
    int n = w >> 2, hd = w & 3;
    const __half2* hp = (const __half2*)(h + (size_t)n * FD + hd * HF);
    const float* sp = a_s + hd * HF;
    const float* dp = a_d + hd * HF;
    float2 v = __half22float2(hp[lane]);
    int e = 2 * lane;
    float s = v.x * sp[e] + v.y * sp[e + 1];
    float d = v.x * dp[e] + v.y * dp[e + 1];
    #pragma unroll
    for (int o = 16; o; o >>= 1) {
        s += __shfl_xor_sync(0xffffffffu, s, o);
        d += __shfl_xor_sync(0xffffffffu, d, o);
    }
    if (lane == 0) { als[n * NH + hd] = s; ald[n * NH + hd] = d; }
}

// ---------------- fused gather: ONE warp per dst node ----------------
__device__ __forceinline__ float lrelu(float x) { return x > 0.f ? x : 0.2f * x; }

struct F8 { float v[8]; };
__device__ __forceinline__ F8 ld_h8(const uint4* hp, size_t idx) {
    uint4 u = hp[idx];
    F8 r;
    float2 f;
    f = __half22float2(*(__half2*)&u.x); r.v[0] = f.x; r.v[1] = f.y;
    f = __half22float2(*(__half2*)&u.y); r.v[2] = f.x; r.v[3] = f.y;
    f = __half22float2(*(__half2*)&u.z); r.v[4] = f.x; r.v[5] = f.y;
    f = __half22float2(*(__half2*)&u.w); r.v[6] = f.x; r.v[7] = f.y;
    return r;
}

__global__ __launch_bounds__(256) void gather_k(
    const int* __restrict__ rowptr, const int* __restrict__ srcs,
    const float* __restrict__ als, const float* __restrict__ ald,
    const __half* __restrict__ h, const float* __restrict__ bias,
    float* __restrict__ out_f32,
    unsigned* __restrict__ out_h16,
    int final_layer)
{
    int w = (blockIdx.x * blockDim.x + threadIdx.x) >> 5;
    int lane = threadIdx.x & 31;
    if (w >= NN) return;
    int dst = w;
    int hd = lane >> 3;
    float aldv = __ldg(ald + dst * NH + hd);
    const uint4* hp = (const uint4*)h;

    float acc[8] = {};
    float den = 0.f;

    {
        float ee = __expf(lrelu(__ldg(als + dst * NH + hd) + aldv));
        F8 v = ld_h8(hp, (size_t)dst * 32 + lane);
        #pragma unroll
        for (int j = 0; j < 8; j++) acc[j] += ee * v.v[j];
        den += ee;
    }

    int beg = rowptr[dst], end = rowptr[dst + 1];
    int i = beg;
    for (; i + 2 <= end; i += 2) {
        int s0 = __ldg(srcs + i), s1 = __ldg(srcs + i + 1);
        float e0 = __expf(lrelu(__ldg(als + s0 * NH + hd) + aldv));
        float e1 = __expf(lrelu(__ldg(als + s1 * NH + hd) + aldv));
        F8 v0 = ld_h8(hp, (size_t)s0 * 32 + lane);
        F8 v1 = ld_h8(hp, (size_t)s1 * 32 + lane);
        #pragma unroll
        for (int j = 0; j < 8; j++) acc[j] += e0 * v0.v[j] + e1 * v1.v[j];
        den += e0 + e1;
    }
    if (i < end) {
        int s0 = __ldg(srcs + i);
        float e0 = __expf(lrelu(__ldg(als + s0 * NH + hd) + aldv));
        F8 v0 = ld_h8(hp, (size_t)s0 * 32 + lane);
        #pragma unroll
        for (int j = 0; j < 8; j++) acc[j] += e0 * v0.v[j];
        den += e0;
    }

    float inv = 1.f / (den + 1e-16f);
    const float4* bp = (const float4*)bias;
    float4 b0 = bp[lane * 2], b1 = bp[lane * 2 + 1];
    float o[8];
    o[0] = acc[0] * inv + b0.x; o[1] = acc[1] * inv + b0.y;
    o[2] = acc[2] * inv + b0.z; o[3] = acc[3] * inv + b0.w;
    o[4] = acc[4] * inv + b1.x; o[5] = acc[5] * inv + b1.y;
    o[6] = acc[6] * inv + b1.z; o[7] = acc[7] * inv + b1.w;

    if (final_layer) {
        float4* op = (float4*)(out_f32 + (size_t)dst * FD);
        op[lane * 2]     = make_float4(o[0], o[1], o[2], o[3]);
        op[lane * 2 + 1] = make_float4(o[4], o[5], o[6], o[7]);
    } else {
        __half2 p0 = __floats2half2_rn(o[0], o[1]);
        __half2 p1 = __floats2half2_rn(o[2], o[3]);
        __half2 p2 = __floats2half2_rn(o[4], o[5]);
        __half2 p3 = __floats2half2_rn(o[6], o[7]);
        ((uint4*)out_h16)[(size_t)dst * 32 + lane] =
            make_uint4(*(unsigned*)&p0, *(unsigned*)&p1,
                       *(unsigned*)&p2, *(unsigned*)&p3);
    }
}

// ---------------- host side ----------------
extern "C" void kernel_launch(void* const* d_in, const int* in_sizes, int n_in,
                              void* d_out, int out_size)
{
    const float* x   = (const float*)d_in[0];
    const int*   ei  = (const int*)  d_in[1];
    const float* W0  = (const float*)d_in[2];
    const float* as0 = (const float*)d_in[3];
    const float* ad0 = (const float*)d_in[4];
    const float* b0  = (const float*)d_in[5];
    const float* W1  = (const float*)d_in[6];
    const float* as1 = (const float*)d_in[7];
    const float* ad1 = (const float*)d_in[8];
    const float* b1  = (const float*)d_in[9];
    const float* W2  = (const float*)d_in[10];
    const float* as2 = (const float*)d_in[11];
    const float* ad2 = (const float*)d_in[12];
    const float* b2  = (const float*)d_in[13];
    float* out = (float*)d_out;

    void *ph, *pin, *pwhi, *pwlo, *pals, *pald, *pdeg, *prp, *pcur, *psrc;
    cudaGetSymbolAddress(&ph,   g_h);
    cudaGetSymbolAddress(&pin,  g_in);
    cudaGetSymbolAddress(&pwhi, g_whi);
    cudaGetSymbolAddress(&pwlo, g_wlo);
    cudaGetSymbolAddress(&pals, g_als);
    cudaGetSymbolAddress(&pald, g_ald);
    cudaGetSymbolAddress(&pdeg, g_deg);
    cudaGetSymbolAddress(&prp,  g_rowptr);
    cudaGetSymbolAddress(&pcur, g_cursor);
    cudaGetSymbolAddress(&psrc, g_srcs);

    __half* h     = (__half*)ph;
    unsigned* ain = (unsigned*)pin;
    unsigned* whi = (unsigned*)pwhi;
    unsigned* wlo = (unsigned*)pwlo;
    float* als    = (float*)pals;
    float* ald    = (float*)pald;
    int* deg      = (int*)pdeg;
    int* rowptr   = (int*)prp;
    int* cursor   = (int*)pcur;
    int* srcs     = (int*)psrc;

    dim3 ggrid((NN + 127) / 128, FD / 128);

    // 1: prep
    prep_k<<<(NN * 64 + 255) / 256, 256>>>(x, ain, W0, W1, W2, whi, wlo, deg);
    // 2: hist
    deg_hist_k<<<(EE + 255) / 256, 256>>>(ei, deg);
    // 3: scan
    scan_k<<<1, 1024>>>(deg, rowptr, cursor);
    // 4: layer-0 GEMM  <-- ncu capture lands here
    gemm_pre_k<<<ggrid, 256>>>(ain, whi, wlo, h, NN);
    // 5: CSR fill
    fill_k<<<(EE + 255) / 256, 256>>>(ei, cursor, srcs);
    // layer 0 rest
    att_k<<<(NN * NH * 32 + 255) / 256, 256>>>(h, as0, ad0, als, ald, NN);
    gather_k<<<(NN * 32 + 255) / 256, 256>>>(rowptr, srcs, als, ald, h, b0, out, ain, 0);
    // layer 1
    gemm_pre_k<<<ggrid, 256>>>(ain, whi + K2 * FD, wlo + K2 * FD, h, NN);
    att_k<<<(NN * NH * 32 + 255) / 256, 256>>>(h, as1, ad1, als, ald, NN);
    gather_k<<<(NN * 32 + 255) / 256, 256>>>(rowptr, srcs, als, ald, h, b1, out, ain, 0);
    // layer 2
    gemm_pre_k<<<ggrid, 256>>>(ain, whi + 2 * K2 * FD, wlo + 2 * K2 * FD, h, NN);
    att_k<<<(NN * NH * 32 + 255) / 256, 256>>>(h, as2, ad2, als, ald, NN);
    gather_k<<<(NN * 32 + 255) / 256, 256>>>(rowptr, srcs, als, ald, h, b2, out, ain, 1);
}

// round 13
// speedup vs baseline: 1.3367x; 1.0476x over previous
#include <cuda_runtime.h>
#include <cuda_fp16.h>
#include <math.h>

#define NN 50000
#define EE 800000
#define FD 256
#define NH 4
#define HF 64
#define K2 (FD / 2)       // 128 packed fp16x2 per row

// ---------------- scratch ----------------
__device__ __half   g_h  [NN * FD];          // per-layer projection (fp16)
__device__ unsigned g_in [NN * K2];          // layer input, fp16 packed (k,k+1)
__device__ unsigned g_whi[3 * K2 * FD];      // W pre-packed [layer][k2][n] fp16 hi
__device__ unsigned g_wlo[3 * K2 * FD];      // W fp16 lo (residual)
__device__ float    g_als[NN * NH];
__device__ float    g_ald[NN * NH];
__device__ int      g_deg[NN];
__device__ int      g_rowptr[NN + 1];
__device__ int      g_cursor[NN];
__device__ int      g_srcs[EE];

__device__ __forceinline__ void splitw(float x, float y, unsigned& hi, unsigned& lo) {
    __half hx = __float2half_rn(x);
    __half hy = __float2half_rn(y);
    float rx = x - __half2float(hx);
    float ry = y - __half2float(hy);
    __half2 h2 = __halves2half2(hx, hy);
    __half2 l2 = __floats2half2_rn(rx, ry);
    hi = *(unsigned*)&h2;
    lo = *(unsigned*)&l2;
}

// ---------------- prep: deg=0, x->fp16, split W (one kernel) ----------------
__global__ void prep_k(const float* __restrict__ x,
                       unsigned* __restrict__ xin,
                       const float* __restrict__ W0, const float* __restrict__ W1,
                       const float* __restrict__ W2,
                       unsigned* __restrict__ whi, unsigned* __restrict__ wlo,
                       int* __restrict__ deg)
{
    int idx = blockIdx.x * blockDim.x + threadIdx.x;
    if (idx < NN) deg[idx] = 0;
    if (idx < 3 * K2 * FD) {
        int l = idx / (K2 * FD);
        int rem = idx - l * (K2 * FD);
        int k2 = rem >> 8, n = rem & 255;
        const float* W = (l == 0) ? W0 : (l == 1) ? W1 : W2;
        float a = W[(2 * k2) * FD + n];
        float b = W[(2 * k2 + 1) * FD + n];
        unsigned h, lw;
        splitw(a, b, h, lw);
        whi[idx] = h;
        wlo[idx] = lw;
    }
    if (idx < NN * 64) {
        float4 v = ((const float4*)x)[idx];
        __half2 p0 = __floats2half2_rn(v.x, v.y);
        __half2 p1 = __floats2half2_rn(v.z, v.w);
        ((uint2*)xin)[idx] = make_uint2(*(unsigned*)&p0, *(unsigned*)&p1);
    }
}

// ---------------- CSR build ----------------
__global__ void deg_hist_k(const int* __restrict__ ei, int* __restrict__ deg) {
    int e = blockIdx.x * blockDim.x + threadIdx.x;
    if (e < EE) atomicAdd(deg + ei[EE + e], 1);
}
__global__ __launch_bounds__(1024) void scan_k(const int* __restrict__ deg,
                                               int* __restrict__ rowptr,
                                               int* __restrict__ cursor) {
    __shared__ int ssum[1024];
    const int CH = 49;
    int t = threadIdx.x;
    int base = t * CH;
    int s = 0;
    for (int i = 0; i < CH; i++) {
        int idx = base + i;
        if (idx < NN) s += deg[idx];
    }
    ssum[t] = s;
    __syncthreads();
    for (int o = 1; o < 1024; o <<= 1) {
        int u = (t >= o) ? ssum[t - o] : 0;
        __syncthreads();
        ssum[t] += u;
        __syncthreads();
    }
    int run = ssum[t] - s;
    for (int i = 0; i < CH; i++) {
        int idx = base + i;
        if (idx <= NN) {
            if (idx < NN) {
                rowptr[idx] = run;
                cursor[idx] = run;
                run += deg[idx];
            } else {
                rowptr[NN] = run;
            }
        }
    }
}
__global__ void fill_k(const int* __restrict__ ei, int* __restrict__ cursor,
                       int* __restrict__ srcs) {
    int e = blockIdx.x * blockDim.x + threadIdx.x;
    if (e >= EE) return;
    int dst = ei[EE + e];
    int pos = atomicAdd(cursor + dst, 1);
    srcs[pos] = ei[e];
}

// ---------------- fp16x2-W GEMM, BM=64, BK=32, 2-stage cp.async ----------------
// C[N,256] = A[N,256](fp16) * (Wh + Wl)[256,256]
// BM=64, BN=128, BK=32 (16 k2) per stage. 256 threads, warp tile 32x32.
#define SA2 20    // A smem row stride in uints (16 + 4 pad) -> conflict-free
#define SB2 136   // B smem row stride in uints (128 + 8 pad) -> conflict-free
#define NIT (K2 / 16)   // 8 k-iterations

#define MMA_F16(c, a, b) \
    asm volatile("mma.sync.aligned.m16n8k16.row.col.f32.f16.f16.f32 " \
                 "{%0,%1,%2,%3}, {%4,%5,%6,%7}, {%8,%9}, {%0,%1,%2,%3};" \
                 : "+f"(c[0]), "+f"(c[1]), "+f"(c[2]), "+f"(c[3]) \
                 : "r"(a[0]), "r"(a[1]), "r"(a[2]), "r"(a[3]), "r"(b[0]), "r"(b[1]))

__device__ __forceinline__ void cp16(unsigned dst, const void* src, bool pred) {
    int bytes = pred ? 16 : 0;
    asm volatile("cp.async.cg.shared.global [%0], [%1], 16, %2;"
                 :: "r"(dst), "l"(src), "r"(bytes));
}
#define CP_COMMIT() asm volatile("cp.async.commit_group;")
#define CP_WAIT(n)  asm volatile("cp.async.wait_group %0;" :: "n"(n))

__global__ __launch_bounds__(256) void gemm_pre_k(
    const unsigned* __restrict__ Ain,
    const unsigned* __restrict__ Whi, const unsigned* __restrict__ Wlo,
    __half* __restrict__ C, int N)
{
    __shared__ unsigned As2[2 * 64 * SA2];
    __shared__ unsigned Bh2[2 * 16 * SB2], Bl2[2 * 16 * SB2];
    int tid = threadIdx.x, lane = tid & 31, wid = tid >> 5;
    int bm = blockIdx.x * 64, bn = blockIdx.y * 128;
    int wm = (wid >> 2) * 32, wn = (wid & 3) * 32;
    int gr = lane >> 2, gc = lane & 3;

    unsigned sA  = (unsigned)__cvta_generic_to_shared(As2);
    unsigned sBh = (unsigned)__cvta_generic_to_shared(Bh2);
    unsigned sBl = (unsigned)__cvta_generic_to_shared(Bl2);

    int ar = tid >> 2, ac = (tid & 3) * 4;       // A: 64 rows x 4 uint4
    int br = tid >> 4, bc = (tid & 15) * 4;      // B: 16 rows x 16 uint4, 1/thread... need 2
    // B tile per stage: 16 k2-rows x 128 uints = 512 uint4 -> 2 per thread
    int br2 = 8 + (tid >> 4);                    // second slot rows 8..23? No: use +8 rows
    bool ap = (bm + ar) < N;
    size_t abase = (size_t)(bm + ar) * K2 + ac;

    float acc[2][4][4] = {};

#define LOAD_STAGE(kb, s) do { \
        cp16(sA  + (unsigned)(((s) * 64 * SA2 + ar * SA2 + ac) * 4), Ain + abase + (kb), ap); \
        { \
            int r0 = tid >> 5, c0 = (tid & 31) * 4; \
            size_t bb0 = (size_t)((kb) + r0) * FD + bn + c0; \
            cp16(sBh + (unsigned)(((s) * 16 * SB2 + r0 * SB2 + c0) * 4), Whi + bb0, true); \
            cp16(sBl + (unsigned)(((s) * 16 * SB2 + r0 * SB2 + c0) * 4), Wlo + bb0, true); \
            int r1 = r0 + 8; \
            size_t bb1 = (size_t)((kb) + r1) * FD + bn + c0; \
            cp16(sBh + (unsigned)(((s) * 16 * SB2 + r1 * SB2 + c0) * 4), Whi + bb1, true); \
            cp16(sBl + (unsigned)(((s) * 16 * SB2 + r1 * SB2 + c0) * 4), Wlo + bb1, true); \
        } \
    } while (0)

    LOAD_STAGE(0, 0); CP_COMMIT();
    LOAD_STAGE(16, 1); CP_COMMIT();

    for (int it = 0; it < NIT; it++) {
        if (it < NIT - 1) { CP_WAIT(1); } else { CP_WAIT(0); }
        __syncthreads();
        int s = it & 1;
        const unsigned* As = As2 + s * 64 * SA2;
        const unsigned* Bs = Bh2 + s * 16 * SB2;
        const unsigned* Bls = Bl2 + s * 16 * SB2;

        #pragma unroll
        for (int g = 0; g < 2; g++) {            // two k16 groups per BK=32
            unsigned ah[2][4], bh[4][2], bl[4][2];
            #pragma unroll
            for (int mt = 0; mt < 2; mt++) {
                int m = wm + mt * 16 + gr;
                const unsigned* p = As + m * SA2 + g * 8 + gc;
                ah[mt][0] = p[0]; ah[mt][1] = p[8 * SA2]; ah[mt][2] = p[4]; ah[mt][3] = p[8 * SA2 + 4];
            }
            #pragma unroll
            for (int nt = 0; nt < 4; nt++) {
                int n = wn + nt * 8 + gr;
                const unsigned* p = Bs + (g * 8 + gc) * SB2 + n;
                const unsigned* q = Bls + (g * 8 + gc) * SB2 + n;
                bh[nt][0] = p[0]; bh[nt][1] = p[4 * SB2];
                bl[nt][0] = q[0]; bl[nt][1] = q[4 * SB2];
            }
            #pragma unroll
            for (int mt = 0; mt < 2; mt++)
                #pragma unroll
                for (int nt = 0; nt < 4; nt++) {
                    MMA_F16(acc[mt][nt], ah[mt], bh[nt]);
                    MMA_F16(acc[mt][nt], ah[mt], bl[nt]);
                }
        }
        __syncthreads();
        if (it + 2 < NIT) { LOAD_STAGE((it + 2) * 16, s); CP_COMMIT(); }
    }

    #pragma unroll
    for (int mt = 0; mt < 2; mt++)
        #pragma unroll
        for (int nt = 0; nt < 4; nt++) {
            int row = bm + wm + mt * 16 + gr;
            int col = bn + wn + nt * 8 + 2 * gc;
            if (row < N)
                *(__half2*)(C + (size_t)row * FD + col) =
                    __floats2half2_rn(acc[mt][nt][0], acc[mt][nt][1]);
            if (row + 8 < N)
                *(__half2*)(C + (size_t)(row + 8) * FD + col) =
                    __floats2half2_rn(acc[mt][nt][2], acc[mt][nt][3]);
        }
}

// ---------------- attention logits: warp per (node, head), fp16 h ----------------
__global__ void att_k(const __half* __restrict__ h,
                      const float* __restrict__ a_s, const float* __restrict__ a_d,
                      float* __restrict__ als, float* __restrict__ ald, int N)
{
    int w = (blockIdx.x * blockDim.x + threadIdx.x) >> 5;
    int lane = threadIdx.x & 31;
    if (w >= N * NH) return;
    int n = w >> 2, hd = w & 3;
    const __half2* hp = (const __half2*)(h + (size_t)n * FD + hd * HF);
    const float* sp = a_s + hd * HF;
    const float* dp = a_d + hd * HF;
    float2 v = __half22float2(hp[lane]);
    int e = 2 * lane;
    float s = v.x * sp[e] + v.y * sp[e + 1];
    float d = v.x * dp[e] + v.y * dp[e + 1];
    #pragma unroll
    for (int o = 16; o; o >>= 1) {
        s += __shfl_xor_sync(0xffffffffu, s, o);
        d += __shfl_xor_sync(0xffffffffu, d, o);
    }
    if (lane == 0) { als[n * NH + hd] = s; ald[n * NH + hd] = d; }
}

// ---------------- fused gather: ONE warp per dst node, 4-edge unroll ----------------
__device__ __forceinline__ float lrelu(float x) { return x > 0.f ? x : 0.2f * x; }

struct F8 { float v[8]; };
__device__ __forceinline__ F8 ld_h8(const uint4* hp, size_t idx) {
    uint4 u = hp[idx];
    F8 r;
    float2 f;
    f = __half22float2(*(__half2*)&u.x); r.v[0] = f.x; r.v[1] = f.y;
    f = __half22float2(*(__half2*)&u.y); r.v[2] = f.x; r.v[3] = f.y;
    f = __half22float2(*(__half2*)&u.z); r.v[4] = f.x; r.v[5] = f.y;
    f = __half22float2(*(__half2*)&u.w); r.v[6] = f.x; r.v[7] = f.y;
    return r;
}

__global__ __launch_bounds__(256) void gather_k(
    const int* __restrict__ rowptr, const int* __restrict__ srcs,
    const float* __restrict__ als, const float* __restrict__ ald,
    const __half* __restrict__ h, const float* __restrict__ bias,
    float* __restrict__ out_f32,
    unsigned* __restrict__ out_h16,
    int final_layer)
{
    int w = (blockIdx.x * blockDim.x + threadIdx.x) >> 5;
    int lane = threadIdx.x & 31;
    if (w >= NN) return;
    int dst = w;
    int hd = lane >> 3;
    float aldv = __ldg(ald + dst * NH + hd);
    const uint4* hp = (const uint4*)h;

    float acc[8] = {};
    float den = 0.f;

    {
        float ee = __expf(lrelu(__ldg(als + dst * NH + hd) + aldv));
        F8 v = ld_h8(hp, (size_t)dst * 32 + lane);
        #pragma unroll
        for (int j = 0; j < 8; j++) acc[j] += ee * v.v[j];
        den += ee;
    }

    int beg = rowptr[dst], end = rowptr[dst + 1];
    int i = beg;
    for (; i + 4 <= end; i += 4) {
        int s0 = __ldg(srcs + i),     s1 = __ldg(srcs + i + 1);
        int s2 = __ldg(srcs + i + 2), s3 = __ldg(srcs + i + 3);
        float e0 = __expf(lrelu(__ldg(als + s0 * NH + hd) + aldv));
        float e1 = __expf(lrelu(__ldg(als + s1 * NH + hd) + aldv));
        float e2 = __expf(lrelu(__ldg(als + s2 * NH + hd) + aldv));
        float e3 = __expf(lrelu(__ldg(als + s3 * NH + hd) + aldv));
        F8 v0 = ld_h8(hp, (size_t)s0 * 32 + lane);
        F8 v1 = ld_h8(hp, (size_t)s1 * 32 + lane);
        F8 v2 = ld_h8(hp, (size_t)s2 * 32 + lane);
        F8 v3 = ld_h8(hp, (size_t)s3 * 32 + lane);
        #pragma unroll
        for (int j = 0; j < 8; j++)
            acc[j] += e0 * v0.v[j] + e1 * v1.v[j] + e2 * v2.v[j] + e3 * v3.v[j];
        den += e0 + e1 + e2 + e3;
    }
    for (; i < end; i++) {
        int s0 = __ldg(srcs + i);
        float e0 = __expf(lrelu(__ldg(als + s0 * NH + hd) + aldv));
        F8 v0 = ld_h8(hp, (size_t)s0 * 32 + lane);
        #pragma unroll
        for (int j = 0; j < 8; j++) acc[j] += e0 * v0.v[j];
        den += e0;
    }

    float inv = 1.f / (den + 1e-16f);
    const float4* bp = (const float4*)bias;
    float4 b0 = bp[lane * 2], b1 = bp[lane * 2 + 1];
    float o[8];
    o[0] = acc[0] * inv + b0.x; o[1] = acc[1] * inv + b0.y;
    o[2] = acc[2] * inv + b0.z; o[3] = acc[3] * inv + b0.w;
    o[4] = acc[4] * inv + b1.x; o[5] = acc[5] * inv + b1.y;
    o[6] = acc[6] * inv + b1.z; o[7] = acc[7] * inv + b1.w;

    if (final_layer) {
        float4* op = (float4*)(out_f32 + (size_t)dst * FD);
        op[lane * 2]     = make_float4(o[0], o[1], o[2], o[3]);
        op[lane * 2 + 1] = make_float4(o[4], o[5], o[6], o[7]);
    } else {
        __half2 p0 = __floats2half2_rn(o[0], o[1]);
        __half2 p1 = __floats2half2_rn(o[2], o[3]);
        __half2 p2 = __floats2half2_rn(o[4], o[5]);
        __half2 p3 = __floats2half2_rn(o[6], o[7]);
        ((uint4*)out_h16)[(size_t)dst * 32 + lane] =
            make_uint4(*(unsigned*)&p0, *(unsigned*)&p1,
                       *(unsigned*)&p2, *(unsigned*)&p3);
    }
}

// ---------------- host side ----------------
extern "C" void kernel_launch(void* const* d_in, const int* in_sizes, int n_in,
                              void* d_out, int out_size)
{
    const float* x   = (const float*)d_in[0];
    const int*   ei  = (const int*)  d_in[1];
    const float* W0  = (const float*)d_in[2];
    const float* as0 = (const float*)d_in[3];
    const float* ad0 = (const float*)d_in[4];
    const float* b0  = (const float*)d_in[5];
    const float* W1  = (const float*)d_in[6];
    const float* as1 = (const float*)d_in[7];
    const float* ad1 = (const float*)d_in[8];
    const float* b1  = (const float*)d_in[9];
    const float* W2  = (const float*)d_in[10];
    const float* as2 = (const float*)d_in[11];
    const float* ad2 = (const float*)d_in[12];
    const float* b2  = (const float*)d_in[13];
    float* out = (float*)d_out;

    void *ph, *pin, *pwhi, *pwlo, *pals, *pald, *pdeg, *prp, *pcur, *psrc;
    cudaGetSymbolAddress(&ph,   g_h);
    cudaGetSymbolAddress(&pin,  g_in);
    cudaGetSymbolAddress(&pwhi, g_whi);
    cudaGetSymbolAddress(&pwlo, g_wlo);
    cudaGetSymbolAddress(&pals, g_als);
    cudaGetSymbolAddress(&pald, g_ald);
    cudaGetSymbolAddress(&pdeg, g_deg);
    cudaGetSymbolAddress(&prp,  g_rowptr);
    cudaGetSymbolAddress(&pcur, g_cursor);
    cudaGetSymbolAddress(&psrc, g_srcs);

    __half* h     = (__half*)ph;
    unsigned* ain = (unsigned*)pin;
    unsigned* whi = (unsigned*)pwhi;
    unsigned* wlo = (unsigned*)pwlo;
    float* als    = (float*)pals;
    float* ald    = (float*)pald;
    int* deg      = (int*)pdeg;
    int* rowptr   = (int*)prp;
    int* cursor   = (int*)pcur;
    int* srcs     = (int*)psrc;

    dim3 ggrid((NN + 63) / 64, FD / 128);

    // 1: prep
    prep_k<<<(NN * 64 + 255) / 256, 256>>>(x, ain, W0, W1, W2, whi, wlo, deg);
    // 2: hist
    deg_hist_k<<<(EE + 255) / 256, 256>>>(ei, deg);
    // 3: scan
    scan_k<<<1, 1024>>>(deg, rowptr, cursor);
    // 4: layer-0 GEMM  <-- ncu capture lands here
    gemm_pre_k<<<ggrid, 256>>>(ain, whi, wlo, h, NN);
    // 5: CSR fill
    fill_k<<<(EE + 255) / 256, 256>>>(ei, cursor, srcs);
    // layer 0 rest
    att_k<<<(NN * NH * 32 + 255) / 256, 256>>>(h, as0, ad0, als, ald, NN);
    gather_k<<<(NN * 32 + 255) / 256, 256>>>(rowptr, srcs, als, ald, h, b0, out, ain, 0);
    // layer 1
    gemm_pre_k<<<ggrid, 256>>>(ain, whi + K2 * FD, wlo + K2 * FD, h, NN);
    att_k<<<(NN * NH * 32 + 255) / 256, 256>>>(h, as1, ad1, als, ald, NN);
    gather_k<<<(NN * 32 + 255) / 256, 256>>>(rowptr, srcs, als, ald, h, b1, out, ain, 0);
    // layer 2
    gemm_pre_k<<<ggrid, 256>>>(ain, whi + 2 * K2 * FD, wlo + 2 * K2 * FD, h, NN);
    att_k<<<(NN * NH * 32 + 255) / 256, 256>>>(h, as2, ad2, als, ald, NN);
    gather_k<<<(NN * 32 + 255) / 256, 256>>>(rowptr, srcs, als, ald, h, b2, out, ain, 1);
}

// round 14
// speedup vs baseline: 1.4994x; 1.1216x over previous
#include <cuda_runtime.h>
#include <cuda_fp16.h>
#include <math.h>

#define NN 50000
#define EE 800000
#define FD 256
#define NH 4
#define HF 64
#define K2 (FD / 2)       // 128 packed fp16x2 per row

// ---------------- scratch ----------------
__device__ __half   g_h  [NN * FD];          // per-layer projection (fp16)
__device__ unsigned g_in [NN * K2];          // layer input, fp16 packed (k,k+1)
__device__ unsigned g_w  [3 * K2 * FD];      // W pre-packed [layer][k2][n] fp16
__device__ float    g_als[NN * NH];
__device__ float    g_ald[NN * NH];
__device__ int      g_deg[NN];
__device__ int      g_rowptr[NN + 1];
__device__ int      g_cursor[NN];
__device__ int      g_srcs[EE];

// ---------------- prep: deg=0, x->fp16, W->fp16 (one kernel) ----------------
__global__ void prep_k(const float* __restrict__ x,
                       unsigned* __restrict__ xin,
                       const float* __restrict__ W0, const float* __restrict__ W1,
                       const float* __restrict__ W2,
                       unsigned* __restrict__ wpk,
                       int* __restrict__ deg)
{
    int idx = blockIdx.x * blockDim.x + threadIdx.x;
    if (idx < NN) deg[idx] = 0;
    if (idx < 3 * K2 * FD) {
        int l = idx / (K2 * FD);
        int rem = idx - l * (K2 * FD);
        int k2 = rem >> 8, n = rem & 255;
        const float* W = (l == 0) ? W0 : (l == 1) ? W1 : W2;
        __half2 p = __floats2half2_rn(W[(2 * k2) * FD + n], W[(2 * k2 + 1) * FD + n]);
        wpk[idx] = *(unsigned*)&p;
    }
    if (idx < NN * 64) {
        float4 v = ((const float4*)x)[idx];
        __half2 p0 = __floats2half2_rn(v.x, v.y);
        __half2 p1 = __floats2half2_rn(v.z, v.w);
        ((uint2*)xin)[idx] = make_uint2(*(unsigned*)&p0, *(unsigned*)&p1);
    }
}

// ---------------- CSR build ----------------
__global__ void deg_hist_k(const int* __restrict__ ei, int* __restrict__ deg) {
    int e = blockIdx.x * blockDim.x + threadIdx.x;
    if (e < EE) atomicAdd(deg + ei[EE + e], 1);
}
__global__ __launch_bounds__(1024) void scan_k(const int* __restrict__ deg,
                                               int* __restrict__ rowptr,
                                               int* __restrict__ cursor) {
    __shared__ int ssum[1024];
    const int CH = 49;
    int t = threadIdx.x;
    int base = t * CH;
    int s = 0;
    for (int i = 0; i < CH; i++) {
        int idx = base + i;
        if (idx < NN) s += deg[idx];
    }
    ssum[t] = s;
    __syncthreads();
    for (int o = 1; o < 1024; o <<= 1) {
        int u = (t >= o) ? ssum[t - o] : 0;
        __syncthreads();
        ssum[t] += u;
        __syncthreads();
    }
    int run = ssum[t] - s;
    for (int i = 0; i < CH; i++) {
        int idx = base + i;
        if (idx <= NN) {
            if (idx < NN) {
                rowptr[idx] = run;
                cursor[idx] = run;
                run += deg[idx];
            } else {
                rowptr[NN] = run;
            }
        }
    }
}
__global__ void fill_k(const int* __restrict__ ei, int* __restrict__ cursor,
                       int* __restrict__ srcs) {
    int e = blockIdx.x * blockDim.x + threadIdx.x;
    if (e >= EE) return;
    int dst = ei[EE + e];
    int pos = atomicAdd(cursor + dst, 1);
    srcs[pos] = ei[e];
}

// ---------------- fp16 GEMM, BM=64, BN=128, BK=32, 2-stage cp.async ----------------
#define SA2 20    // A smem row stride in uints (16 + 4 pad) -> conflict-free
#define SB2 136   // B smem row stride in uints (128 + 8 pad) -> conflict-free
#define NIT (K2 / 16)   // 8 k-iterations

#define MMA_F16(c, a, b) \
    asm volatile("mma.sync.aligned.m16n8k16.row.col.f32.f16.f16.f32 " \
                 "{%0,%1,%2,%3}, {%4,%5,%6,%7}, {%8,%9}, {%0,%1,%2,%3};" \
                 : "+f"(c[0]), "+f"(c[1]), "+f"(c[2]), "+f"(c[3]) \
                 : "r"(a[0]), "r"(a[1]), "r"(a[2]), "r"(a[3]), "r"(b[0]), "r"(b[1]))

__device__ __forceinline__ void cp16(unsigned dst, const void* src, bool pred) {
    int bytes = pred ? 16 : 0;
    asm volatile("cp.async.cg.shared.global [%0], [%1], 16, %2;"
                 :: "r"(dst), "l"(src), "r"(bytes));
}
#define CP_COMMIT() asm volatile("cp.async.commit_group;")
#define CP_WAIT(n)  asm volatile("cp.async.wait_group %0;" :: "n"(n))

__global__ __launch_bounds__(256) void gemm_pre_k(
    const unsigned* __restrict__ Ain,
    const unsigned* __restrict__ Wpk,
    __half* __restrict__ C, int N)
{
    __shared__ unsigned As2[2 * 64 * SA2];
    __shared__ unsigned Bs2[2 * 16 * SB2];
    int tid = threadIdx.x, lane = tid & 31, wid = tid >> 5;
    int bm = blockIdx.x * 64, bn = blockIdx.y * 128;
    int wm = (wid >> 2) * 32, wn = (wid & 3) * 32;
    int gr = lane >> 2, gc = lane & 3;

    unsigned sA = (unsigned)__cvta_generic_to_shared(As2);
    unsigned sB = (unsigned)__cvta_generic_to_shared(Bs2);

    int ar = tid >> 2, ac = (tid & 3) * 4;       // A: 64 rows x 4 uint4
    bool ap = (bm + ar) < N;
    size_t abase = (size_t)(bm + ar) * K2 + ac;

    float acc[2][4][4] = {};

#define LOAD_STAGE(kb, s) do { \
        cp16(sA + (unsigned)(((s) * 64 * SA2 + ar * SA2 + ac) * 4), Ain + abase + (kb), ap); \
        { \
            int r0 = tid >> 5, c0 = (tid & 31) * 4; \
            size_t bb0 = (size_t)((kb) + r0) * FD + bn + c0; \
            cp16(sB + (unsigned)(((s) * 16 * SB2 + r0 * SB2 + c0) * 4), Wpk + bb0, true); \
            int r1 = r0 + 8; \
            size_t bb1 = (size_t)((kb) + r1) * FD + bn + c0; \
            cp16(sB + (unsigned)(((s) * 16 * SB2 + r1 * SB2 + c0) * 4), Wpk + bb1, true); \
        } \
    } while (0)

    LOAD_STAGE(0, 0); CP_COMMIT();
    LOAD_STAGE(16, 1); CP_COMMIT();

    for (int it = 0; it < NIT; it++) {
        if (it < NIT - 1) { CP_WAIT(1); } else { CP_WAIT(0); }
        __syncthreads();
        int s = it & 1;
        const unsigned* As = As2 + s * 64 * SA2;
        const unsigned* Bs = Bs2 + s * 16 * SB2;

        #pragma unroll
        for (int g = 0; g < 2; g++) {            // two k16 groups per BK=32
            unsigned ah[2][4], bh[4][2];
            #pragma unroll
            for (int mt = 0; mt < 2; mt++) {
                int m = wm + mt * 16 + gr;
                const unsigned* p = As + m * SA2 + g * 8 + gc;
                ah[mt][0] = p[0]; ah[mt][1] = p[8 * SA2]; ah[mt][2] = p[4]; ah[mt][3] = p[8 * SA2 + 4];
            }
            #pragma unroll
            for (int nt = 0; nt < 4; nt++) {
                int n = wn + nt * 8 + gr;
                const unsigned* p = Bs + (g * 8 + gc) * SB2 + n;
                bh[nt][0] = p[0]; bh[nt][1] = p[4 * SB2];
            }
            #pragma unroll
            for (int mt = 0; mt < 2; mt++)
                #pragma unroll
                for (int nt = 0; nt < 4; nt++)
                    MMA_F16(acc[mt][nt], ah[mt], bh[nt]);
        }
        __syncthreads();
        if (it + 2 < NIT) { LOAD_STAGE((it + 2) * 16, s); CP_COMMIT(); }
    }

    #pragma unroll
    for (int mt = 0; mt < 2; mt++)
        #pragma unroll
        for (int nt = 0; nt < 4; nt++) {
            int row = bm + wm + mt * 16 + gr;
            int col = bn + wn + nt * 8 + 2 * gc;
            if (row < N)
                *(__half2*)(C + (size_t)row * FD + col) =
                    __floats2half2_rn(acc[mt][nt][0], acc[mt][nt][1]);
            if (row + 8 < N)
                *(__half2*)(C + (size_t)(row + 8) * FD + col) =
                    __floats2half2_rn(acc[mt][nt][2], acc[mt][nt][3]);
        }
}

// ---------------- attention logits: warp per (node, head), fp16 h ----------------
__global__ void att_k(const __half* __restrict__ h,
                      const float* __restrict__ a_s, const float* __restrict__ a_d,
                      float* __restrict__ als, float* __restrict__ ald, int N)
{
    int w = (blockIdx.x * blockDim.x + threadIdx.x) >> 5;
    int lane = threadIdx.x & 31;
    if (w >= N * NH) return;
    int n = w >> 2, hd = w & 3;
    const __half2* hp = (const __half2*)(h + (size_t)n * FD + hd * HF);
    const float* sp = a_s + hd * HF;
    const float* dp = a_d + hd * HF;
    float2 v = __half22float2(hp[lane]);
    int e = 2 * lane;
    float s = v.x * sp[e] + v.y * sp[e + 1];
    float d = v.x * dp[e] + v.y * dp[e + 1];
    #pragma unroll
    for (int o = 16; o; o >>= 1) {
        s += __shfl_xor_sync(0xffffffffu, s, o);
        d += __shfl_xor_sync(0xffffffffu, d, o);
    }
    if (lane == 0) { als[n * NH + hd] = s; ald[n * NH + hd] = d; }
}

// ---------------- fused gather: ONE warp per dst node, 4-edge unroll ----------------
__device__ __forceinline__ float lrelu(float x) { return x > 0.f ? x : 0.2f * x; }

struct F8 { float v[8]; };
__device__ __forceinline__ F8 ld_h8(const uint4* hp, size_t idx) {
    uint4 u = hp[idx];
    F8 r;
    float2 f;
    f = __half22float2(*(__half2*)&u.x); r.v[0] = f.x; r.v[1] = f.y;
    f = __half22float2(*(__half2*)&u.y); r.v[2] = f.x; r.v[3] = f.y;
    f = __half22float2(*(__half2*)&u.z); r.v[4] = f.x; r.v[5] = f.y;
    f = __half22float2(*(__half2*)&u.w); r.v[6] = f.x; r.v[7] = f.y;
    return r;
}

__global__ __launch_bounds__(256) void gather_k(
    const int* __restrict__ rowptr, const int* __restrict__ srcs,
    const float* __restrict__ als, const float* __restrict__ ald,
    const __half* __restrict__ h, const float* __restrict__ bias,
    float* __restrict__ out_f32,
    unsigned* __restrict__ out_h16,
    int final_layer)
{
    int w = (blockIdx.x * blockDim.x + threadIdx.x) >> 5;
    int lane = threadIdx.x & 31;
    if (w >= NN) return;
    int dst = w;
    int hd = lane >> 3;
    float aldv = __ldg(ald + dst * NH + hd);
    const uint4* hp = (const uint4*)h;

    float acc[8] = {};
    float den = 0.f;

    {
        float ee = __expf(lrelu(__ldg(als + dst * NH + hd) + aldv));
        F8 v = ld_h8(hp, (size_t)dst * 32 + lane);
        #pragma unroll
        for (int j = 0; j < 8; j++) acc[j] += ee * v.v[j];
        den += ee;
    }

    int beg = rowptr[dst], end = rowptr[dst + 1];
    int i = beg;
    for (; i + 4 <= end; i += 4) {
        int s0 = __ldg(srcs + i),     s1 = __ldg(srcs + i + 1);
        int s2 = __ldg(srcs + i + 2), s3 = __ldg(srcs + i + 3);
        float e0 = __expf(lrelu(__ldg(als + s0 * NH + hd) + aldv));
        float e1 = __expf(lrelu(__ldg(als + s1 * NH + hd) + aldv));
        float e2 = __expf(lrelu(__ldg(als + s2 * NH + hd) + aldv));
        float e3 = __expf(lrelu(__ldg(als + s3 * NH + hd) + aldv));
        F8 v0 = ld_h8(hp, (size_t)s0 * 32 + lane);
        F8 v1 = ld_h8(hp, (size_t)s1 * 32 + lane);
        F8 v2 = ld_h8(hp, (size_t)s2 * 32 + lane);
        F8 v3 = ld_h8(hp, (size_t)s3 * 32 + lane);
        #pragma unroll
        for (int j = 0; j < 8; j++)
            acc[j] += e0 * v0.v[j] + e1 * v1.v[j] + e2 * v2.v[j] + e3 * v3.v[j];
        den += e0 + e1 + e2 + e3;
    }
    for (; i < end; i++) {
        int s0 = __ldg(srcs + i);
        float e0 = __expf(lrelu(__ldg(als + s0 * NH + hd) + aldv));
        F8 v0 = ld_h8(hp, (size_t)s0 * 32 + lane);
        #pragma unroll
        for (int j = 0; j < 8; j++) acc[j] += e0 * v0.v[j];
        den += e0;
    }

    float inv = 1.f / (den + 1e-16f);
    const float4* bp = (const float4*)bias;
    float4 b0 = bp[lane * 2], b1 = bp[lane * 2 + 1];
    float o[8];
    o[0] = acc[0] * inv + b0.x; o[1] = acc[1] * inv + b0.y;
    o[2] = acc[2] * inv + b0.z; o[3] = acc[3] * inv + b0.w;
    o[4] = acc[4] * inv + b1.x; o[5] = acc[5] * inv + b1.y;
    o[6] = acc[6] * inv + b1.z; o[7] = acc[7] * inv + b1.w;

    if (final_layer) {
        float4* op = (float4*)(out_f32 + (size_t)dst * FD);
        op[lane * 2]     = make_float4(o[0], o[1], o[2], o[3]);
        op[lane * 2 + 1] = make_float4(o[4], o[5], o[6], o[7]);
    } else {
        __half2 p0 = __floats2half2_rn(o[0], o[1]);
        __half2 p1 = __floats2half2_rn(o[2], o[3]);
        __half2 p2 = __floats2half2_rn(o[4], o[5]);
        __half2 p3 = __floats2half2_rn(o[6], o[7]);
        ((uint4*)out_h16)[(size_t)dst * 32 + lane] =
            make_uint4(*(unsigned*)&p0, *(unsigned*)&p1,
                       *(unsigned*)&p2, *(unsigned*)&p3);
    }
}

// ---------------- host side ----------------
extern "C" void kernel_launch(void* const* d_in, const int* in_sizes, int n_in,
                              void* d_out, int out_size)
{
    const float* x   = (const float*)d_in[0];
    const int*   ei  = (const int*)  d_in[1];
    const float* W0  = (const float*)d_in[2];
    const float* as0 = (const float*)d_in[3];
    const float* ad0 = (const float*)d_in[4];
    const float* b0  = (const float*)d_in[5];
    const float* W1  = (const float*)d_in[6];
    const float* as1 = (const float*)d_in[7];
    const float* ad1 = (const float*)d_in[8];
    const float* b1  = (const float*)d_in[9];
    const float* W2  = (const float*)d_in[10];
    const float* as2 = (const float*)d_in[11];
    const float* ad2 = (const float*)d_in[12];
    const float* b2  = (const float*)d_in[13];
    float* out = (float*)d_out;

    void *ph, *pin, *pw, *pals, *pald, *pdeg, *prp, *pcur, *psrc;
    cudaGetSymbolAddress(&ph,   g_h);
    cudaGetSymbolAddress(&pin,  g_in);
    cudaGetSymbolAddress(&pw,   g_w);
    cudaGetSymbolAddress(&pals, g_als);
    cudaGetSymbolAddress(&pald, g_ald);
    cudaGetSymbolAddress(&pdeg, g_deg);
    cudaGetSymbolAddress(&prp,  g_rowptr);
    cudaGetSymbolAddress(&pcur, g_cursor);
    cudaGetSymbolAddress(&psrc, g_srcs);

    __half* h     = (__half*)ph;
    unsigned* ain = (unsigned*)pin;
    unsigned* wpk = (unsigned*)pw;
    float* als    = (float*)pals;
    float* ald    = (float*)pald;
    int* deg      = (int*)pdeg;
    int* rowptr   = (int*)prp;
    int* cursor   = (int*)pcur;
    int* srcs     = (int*)psrc;

    dim3 ggrid((NN + 63) / 64, FD / 128);

    // 1: prep
    prep_k<<<(NN * 64 + 255) / 256, 256>>>(x, ain, W0, W1, W2, wpk, deg);
    // 2: hist
    deg_hist_k<<<(EE + 255) / 256, 256>>>(ei, deg);
    // 3: scan
    scan_k<<<1, 1024>>>(deg, rowptr, cursor);
    // 4: layer-0 GEMM  <-- ncu capture lands here
    gemm_pre_k<<<ggrid, 256>>>(ain, wpk, h, NN);
    // 5: CSR fill
    fill_k<<<(EE + 255) / 256, 256>>>(ei, cursor, srcs);
    // layer 0 rest
    att_k<<<(NN * NH * 32 + 255) / 256, 256>>>(h, as0, ad0, als, ald, NN);
    gather_k<<<(NN * 32 + 255) / 256, 256>>>(rowptr, srcs, als, ald, h, b0, out, ain, 0);
    // layer 1
    gemm_pre_k<<<ggrid, 256>>>(ain, wpk + K2 * FD, h, NN);
    att_k<<<(NN * NH * 32 + 255) / 256, 256>>>(h, as1, ad1, als, ald, NN);
    gather_k<<<(NN * 32 + 255) / 256, 256>>>(rowptr, srcs, als, ald, h, b1, out, ain, 0);
    // layer 2
    gemm_pre_k<<<ggrid, 256>>>(ain, wpk + 2 * K2 * FD, h, NN);
    att_k<<<(NN * NH * 32 + 255) / 256, 256>>>(h, as2, ad2, als, ald, NN);
    gather_k<<<(NN * 32 + 255) / 256, 256>>>(rowptr, srcs, als, ald, h, b2, out, ain, 1);
}

// round 16
// speedup vs baseline: 1.5124x; 1.0087x over previous
#include <cuda_runtime.h>
#include <cuda_fp16.h>
#include <math.h>

#define NN 50000
#define EE 800000
#define FD 256
#define NH 4
#define HF 64
#define K2 (FD / 2)       // 128 packed fp16x2 per row

// ---------------- scratch ----------------
__device__ __half   g_h  [NN * FD];          // per-layer projection (fp16)
__device__ unsigned g_in [NN * K2];          // layer input, fp16 packed (k,k+1)
__device__ unsigned g_w  [3 * K2 * FD];      // W pre-packed [layer][k2][n] fp16
__device__ float    g_als[NN * NH];
__device__ float    g_ald[NN * NH];
__device__ int      g_deg[NN];
__device__ int      g_rowptr[NN + 1];
__device__ int      g_cursor[NN];
__device__ int      g_srcs[EE];

// ---------------- prep: deg=0, x->fp16, W->fp16 (one kernel) ----------------
__global__ void prep_k(const float* __restrict__ x,
                       unsigned* __restrict__ xin,
                       const float* __restrict__ W0, const float* __restrict__ W1,
                       const float* __restrict__ W2,
                       unsigned* __restrict__ wpk,
                       int* __restrict__ deg)
{
    int idx = blockIdx.x * blockDim.x + threadIdx.x;
    if (idx < NN) deg[idx] = 0;
    if (idx < 3 * K2 * FD) {
        int l = idx / (K2 * FD);
        int rem = idx - l * (K2 * FD);
        int k2 = rem >> 8, n = rem & 255;
        const float* W = (l == 0) ? W0 : (l == 1) ? W1 : W2;
        __half2 p = __floats2half2_rn(W[(2 * k2) * FD + n], W[(2 * k2 + 1) * FD + n]);
        wpk[idx] = *(unsigned*)&p;
    }
    if (idx < NN * 64) {
        float4 v = ((const float4*)x)[idx];
        __half2 p0 = __floats2half2_rn(v.x, v.y);
        __half2 p1 = __floats2half2_rn(v.z, v.w);
        ((uint2*)xin)[idx] = make_uint2(*(unsigned*)&p0, *(unsigned*)&p1);
    }
}

// ---------------- CSR build ----------------
__global__ void deg_hist_k(const int* __restrict__ ei, int* __restrict__ deg) {
    int e = blockIdx.x * blockDim.x + threadIdx.x;
    if (e < EE) atomicAdd(deg + ei[EE + e], 1);
}
__global__ __launch_bounds__(1024) void scan_k(const int* __restrict__ deg,
                                               int* __restrict__ rowptr,
                                               int* __restrict__ cursor) {
    __shared__ int ssum[1024];
    const int CH = 49;
    int t = threadIdx.x;
    int base = t * CH;
    int s = 0;
    for (int i = 0; i < CH; i++) {
        int idx = base + i;
        if (idx < NN) s += deg[idx];
    }
    ssum[t] = s;
    __syncthreads();
    for (int o = 1; o < 1024; o <<= 1) {
        int u = (t >= o) ? ssum[t - o] : 0;
        __syncthreads();
        ssum[t] += u;
        __syncthreads();
    }
    int run = ssum[t] - s;
    for (int i = 0; i < CH; i++) {
        int idx = base + i;
        if (idx <= NN) {
            if (idx < NN) {
                rowptr[idx] = run;
                cursor[idx] = run;
                run += deg[idx];
            } else {
                rowptr[NN] = run;
            }
        }
    }
}
__global__ void fill_k(const int* __restrict__ ei, int* __restrict__ cursor,
                       int* __restrict__ srcs) {
    int e = blockIdx.x * blockDim.x + threadIdx.x;
    if (e >= EE) return;
    int dst = ei[EE + e];
    int pos = atomicAdd(cursor + dst, 1);
    srcs[pos] = ei[e];
}

// ---------------- fp16 GEMM, BM=64, BN=128, BK=32, 2-stage cp.async ----------------
#define SA2 20    // A smem row stride in uints (16 + 4 pad) -> conflict-free
#define SB2 136   // B smem row stride in uints (128 + 8 pad) -> conflict-free
#define NIT (K2 / 16)   // 8 k-iterations

#define MMA_F16(c, a, b) \
    asm volatile("mma.sync.aligned.m16n8k16.row.col.f32.f16.f16.f32 " \
                 "{%0,%1,%2,%3}, {%4,%5,%6,%7}, {%8,%9}, {%0,%1,%2,%3};" \
                 : "+f"(c[0]), "+f"(c[1]), "+f"(c[2]), "+f"(c[3]) \
                 : "r"(a[0]), "r"(a[1]), "r"(a[2]), "r"(a[3]), "r"(b[0]), "r"(b[1]))

__device__ __forceinline__ void cp16(unsigned dst, const void* src, bool pred) {
    int bytes = pred ? 16 : 0;
    asm volatile("cp.async.cg.shared.global [%0], [%1], 16, %2;"
                 :: "r"(dst), "l"(src), "r"(bytes));
}
#define CP_COMMIT() asm volatile("cp.async.commit_group;")
#define CP_WAIT(n)  asm volatile("cp.async.wait_group %0;" :: "n"(n))

__global__ __launch_bounds__(256) void gemm_pre_k(
    const unsigned* __restrict__ Ain,
    const unsigned* __restrict__ Wpk,
    __half* __restrict__ C, int N)
{
    __shared__ unsigned As2[2 * 64 * SA2];
    __shared__ unsigned Bs2[2 * 16 * SB2];
    int tid = threadIdx.x, lane = tid & 31, wid = tid >> 5;
    int bm = blockIdx.x * 64, bn = blockIdx.y * 128;
    int wm = (wid >> 2) * 32, wn = (wid & 3) * 32;
    int gr = lane >> 2, gc = lane & 3;

    unsigned sA = (unsigned)__cvta_generic_to_shared(As2);
    unsigned sB = (unsigned)__cvta_generic_to_shared(Bs2);

    int ar = tid >> 2, ac = (tid & 3) * 4;       // A: 64 rows x 4 uint4
    bool ap = (bm + ar) < N;
    size_t abase = (size_t)(bm + ar) * K2 + ac;

    float acc[2][4][4] = {};

#define LOAD_STAGE(kb, s) do { \
        cp16(sA + (unsigned)(((s) * 64 * SA2 + ar * SA2 + ac) * 4), Ain + abase + (kb), ap); \
        { \
            int r0 = tid >> 5, c0 = (tid & 31) * 4; \
            size_t bb0 = (size_t)((kb) + r0) * FD + bn + c0; \
            cp16(sB + (unsigned)(((s) * 16 * SB2 + r0 * SB2 + c0) * 4), Wpk + bb0, true); \
            int r1 = r0 + 8; \
            size_t bb1 = (size_t)((kb) + r1) * FD + bn + c0; \
            cp16(sB + (unsigned)(((s) * 16 * SB2 + r1 * SB2 + c0) * 4), Wpk + bb1, true); \
        } \
    } while (0)

    LOAD_STAGE(0, 0); CP_COMMIT();
    LOAD_STAGE(16, 1); CP_COMMIT();

    for (int it = 0; it < NIT; it++) {
        if (it < NIT - 1) { CP_WAIT(1); } else { CP_WAIT(0); }
        __syncthreads();
        int s = it & 1;
        const unsigned* As = As2 + s * 64 * SA2;
        const unsigned* Bs = Bs2 + s * 16 * SB2;

        #pragma unroll
        for (int g = 0; g < 2; g++) {            // two k16 groups per BK=32
            unsigned ah[2][4], bh[4][2];
            #pragma unroll
            for (int mt = 0; mt < 2; mt++) {
                int m = wm + mt * 16 + gr;
                const unsigned* p = As + m * SA2 + g * 8 + gc;
                ah[mt][0] = p[0]; ah[mt][1] = p[8 * SA2]; ah[mt][2] = p[4]; ah[mt][3] = p[8 * SA2 + 4];
            }
            #pragma unroll
            for (int nt = 0; nt < 4; nt++) {
                int n = wn + nt * 8 + gr;
                const unsigned* p = Bs + (g * 8 + gc) * SB2 + n;
                bh[nt][0] = p[0]; bh[nt][1] = p[4 * SB2];
            }
            #pragma unroll
            for (int mt = 0; mt < 2; mt++)
                #pragma unroll
                for (int nt = 0; nt < 4; nt++)
                    MMA_F16(acc[mt][nt], ah[mt], bh[nt]);
        }
        __syncthreads();
        if (it + 2 < NIT) { LOAD_STAGE((it + 2) * 16, s); CP_COMMIT(); }
    }

    #pragma unroll
    for (int mt = 0; mt < 2; mt++)
        #pragma unroll
        for (int nt = 0; nt < 4; nt++) {
            int row = bm + wm + mt * 16 + gr;
            int col = bn + wn + nt * 8 + 2 * gc;
            if (row < N)
                *(__half2*)(C + (size_t)row * FD + col) =
                    __floats2half2_rn(acc[mt][nt][0], acc[mt][nt][1]);
            if (row + 8 < N)
                *(__half2*)(C + (size_t)(row + 8) * FD + col) =
                    __floats2half2_rn(acc[mt][nt][2], acc[mt][nt][3]);
        }
}

// ---------------- attention logits: warp per (node, head), fp16 h ----------------
__global__ void att_k(const __half* __restrict__ h,
                      const float* __restrict__ a_s, const float* __restrict__ a_d,
                      float* __restrict__ als, float* __restrict__ ald, int N)
{
    int w = (blockIdx.x * blockDim.x + threadIdx.x) >> 5;
    int lane = threadIdx.x & 31;
    if (w >= N * NH) return;
    int n = w >> 2, hd = w & 3;
    const __half2* hp = (const __half2*)(h + (size_t)n * FD + hd * HF);
    const float* sp = a_s + hd * HF;
    const float* dp = a_d + hd * HF;
    float2 v = __half22float2(hp[lane]);
    int e = 2 * lane;
    float s = v.x * sp[e] + v.y * sp[e + 1];
    float d = v.x * dp[e] + v.y * dp[e + 1];
    #pragma unroll
    for (int o = 16; o; o >>= 1) {
        s += __shfl_xor_sync(0xffffffffu, s, o);
        d += __shfl_xor_sync(0xffffffffu, d, o);
    }
    if (lane == 0) { als[n * NH + hd] = s; ald[n * NH + hd] = d; }
}

// ---------------- fused gather: warp per dst node, 64-thread blocks ----------------
// Small blocks (2 warps) so SM resources recycle at fine granularity -> the HW
// block scheduler load-balances the Poisson degree distribution across nodes.
__device__ __forceinline__ float lrelu(float x) { return x > 0.f ? x : 0.2f * x; }

struct F8 { float v[8]; };
__device__ __forceinline__ F8 ld_h8(const uint4* hp, size_t idx) {
    uint4 u = hp[idx];
    F8 r;
    float2 f;
    f = __half22float2(*(__half2*)&u.x); r.v[0] = f.x; r.v[1] = f.y;
    f = __half22float2(*(__half2*)&u.y); r.v[2] = f.x; r.v[3] = f.y;
    f = __half22float2(*(__half2*)&u.z); r.v[4] = f.x; r.v[5] = f.y;
    f = __half22float2(*(__half2*)&u.w); r.v[6] = f.x; r.v[7] = f.y;
    return r;
}

__global__ __launch_bounds__(64) void gather_k(
    const int* __restrict__ rowptr, const int* __restrict__ srcs,
    const float* __restrict__ als, const float* __restrict__ ald,
    const __half* __restrict__ h, const float* __restrict__ bias,
    float* __restrict__ out_f32,
    unsigned* __restrict__ out_h16,
    int final_layer)
{
    int w = (blockIdx.x * blockDim.x + threadIdx.x) >> 5;
    int lane = threadIdx.x & 31;
    if (w >= NN) return;
    int dst = w;
    int hd = lane >> 3;
    float aldv = __ldg(ald + dst * NH + hd);
    const uint4* hp = (const uint4*)h;

    float acc[8] = {};
    float den = 0.f;

    {
        float ee = __expf(lrelu(__ldg(als + dst * NH + hd) + aldv));
        F8 v = ld_h8(hp, (size_t)dst * 32 + lane);
        #pragma unroll
        for (int j = 0; j < 8; j++) acc[j] += ee * v.v[j];
        den += ee;
    }

    int beg = rowptr[dst], end = rowptr[dst + 1];
    int i = beg;
    for (; i + 4 <= end; i += 4) {
        int s0 = __ldg(srcs + i),     s1 = __ldg(srcs + i + 1);
        int s2 = __ldg(srcs + i + 2), s3 = __ldg(srcs + i + 3);
        float e0 = __expf(lrelu(__ldg(als + s0 * NH + hd) + aldv));
        float e1 = __expf(lrelu(__ldg(als + s1 * NH + hd) + aldv));
        float e2 = __expf(lrelu(__ldg(als + s2 * NH + hd) + aldv));
        float e3 = __expf(lrelu(__ldg(als + s3 * NH + hd) + aldv));
        F8 v0 = ld_h8(hp, (size_t)s0 * 32 + lane);
        F8 v1 = ld_h8(hp, (size_t)s1 * 32 + lane);
        F8 v2 = ld_h8(hp, (size_t)s2 * 32 + lane);
        F8 v3 = ld_h8(hp, (size_t)s3 * 32 + lane);
        #pragma unroll
        for (int j = 0; j < 8; j++)
            acc[j] += e0 * v0.v[j] + e1 * v1.v[j] + e2 * v2.v[j] + e3 * v3.v[j];
        den += e0 + e1 + e2 + e3;
    }
    for (; i < end; i++) {
        int s0 = __ldg(srcs + i);
        float e0 = __expf(lrelu(__ldg(als + s0 * NH + hd) + aldv));
        F8 v0 = ld_h8(hp, (size_t)s0 * 32 + lane);
        #pragma unroll
        for (int j = 0; j < 8; j++) acc[j] += e0 * v0.v[j];
        den += e0;
    }

    float inv = 1.f / (den + 1e-16f);
    const float4* bp = (const float4*)bias;
    float4 b0 = bp[lane * 2], b1 = bp[lane * 2 + 1];
    float o[8];
    o[0] = acc[0] * inv + b0.x; o[1] = acc[1] * inv + b0.y;
    o[2] = acc[2] * inv + b0.z; o[3] = acc[3] * inv + b0.w;
    o[4] = acc[4] * inv + b1.x; o[5] = acc[5] * inv + b1.y;
    o[6] = acc[6] * inv + b1.z; o[7] = acc[7] * inv + b1.w;

    if (final_layer) {
        float4* op = (float4*)(out_f32 + (size_t)dst * FD);
        op[lane * 2]     = make_float4(o[0], o[1], o[2], o[3]);
        op[lane * 2 + 1] = make_float4(o[4], o[5], o[6], o[7]);
    } else {
        __half2 p0 = __floats2half2_rn(o[0], o[1]);
        __half2 p1 = __floats2half2_rn(o[2], o[3]);
        __half2 p2 = __floats2half2_rn(o[4], o[5]);
        __half2 p3 = __floats2half2_rn(o[6], o[7]);
        ((uint4*)out_h16)[(size_t)dst * 32 + lane] =
            make_uint4(*(unsigned*)&p0, *(unsigned*)&p1,
                       *(unsigned*)&p2, *(unsigned*)&p3);
    }
}

// ---------------- host side ----------------
extern "C" void kernel_launch(void* const* d_in, const int* in_sizes, int n_in,
                              void* d_out, int out_size)
{
    const float* x   = (const float*)d_in[0];
    const int*   ei  = (const int*)  d_in[1];
    const float* W0  = (const float*)d_in[2];
    const float* as0 = (const float*)d_in[3];
    const float* ad0 = (const float*)d_in[4];
    const float* b0  = (const float*)d_in[5];
    const float* W1  = (const float*)d_in[6];
    const float* as1 = (const float*)d_in[7];
    const float* ad1 = (const float*)d_in[8];
    const float* b1  = (const float*)d_in[9];
    const float* W2  = (const float*)d_in[10];
    const float* as2 = (const float*)d_in[11];
    const float* ad2 = (const float*)d_in[12];
    const float* b2  = (const float*)d_in[13];
    float* out = (float*)d_out;

    void *ph, *pin, *pw, *pals, *pald, *pdeg, *prp, *pcur, *psrc;
    cudaGetSymbolAddress(&ph,   g_h);
    cudaGetSymbolAddress(&pin,  g_in);
    cudaGetSymbolAddress(&pw,   g_w);
    cudaGetSymbolAddress(&pals, g_als);
    cudaGetSymbolAddress(&pald, g_ald);
    cudaGetSymbolAddress(&pdeg, g_deg);
    cudaGetSymbolAddress(&prp,  g_rowptr);
    cudaGetSymbolAddress(&pcur, g_cursor);
    cudaGetSymbolAddress(&psrc, g_srcs);

    __half* h     = (__half*)ph;
    unsigned* ain = (unsigned*)pin;
    unsigned* wpk = (unsigned*)pw;
    float* als    = (float*)pals;
    float* ald    = (float*)pald;
    int* deg      = (int*)pdeg;
    int* rowptr   = (int*)prp;
    int* cursor   = (int*)pcur;
    int* srcs     = (int*)psrc;

    dim3 ggrid((NN + 63) / 64, FD / 128);
    int ggath = (NN * 32 + 63) / 64;    // 64-thread blocks, warp per node

    // 1: prep
    prep_k<<<(NN * 64 + 255) / 256, 256>>>(x, ain, W0, W1, W2, wpk, deg);
    // 2: hist
    deg_hist_k<<<(EE + 255) / 256, 256>>>(ei, deg);
    // 3: scan
    scan_k<<<1, 1024>>>(deg, rowptr, cursor);
    // 4: layer-0 GEMM  <-- ncu capture lands here
    gemm_pre_k<<<ggrid, 256>>>(ain, wpk, h, NN);
    // 5: CSR fill
    fill_k<<<(EE + 255) / 256, 256>>>(ei, cursor, srcs);
    // layer 0 rest
    att_k<<<(NN * NH * 32 + 255) / 256, 256>>>(h, as0, ad0, als, ald, NN);
    gather_k<<<ggath, 64>>>(rowptr, srcs, als, ald, h, b0, out, ain, 0);
    // layer 1
    gemm_pre_k<<<ggrid, 256>>>(ain, wpk + K2 * FD, h, NN);
    att_k<<<(NN * NH * 32 + 255) / 256, 256>>>(h, as1, ad1, als, ald, NN);
    gather_k<<<ggath, 64>>>(rowptr, srcs, als, ald, h, b1, out, ain, 0);
    // layer 2
    gemm_pre_k<<<ggrid, 256>>>(ain, wpk + 2 * K2 * FD, h, NN);
    att_k<<<(NN * NH * 32 + 255) / 256, 256>>>(h, as2, ad2, als, ald, NN);
    gather_k<<<ggath, 64>>>(rowptr, srcs, als, ald, h, b2, out, ain, 1);
}